// round 5
// baseline (speedup 1.0000x reference)
#include <cuda_runtime.h>
#include <cstdint>
#include <cstddef>

// Problem constants (reference: N=50000, D=128, E=800000, A=5)
#define NMAX 50000
#define DD 128
#define AA 5
#define HH 64

// ---------------- scratch (static device globals) ----------------------------
__device__ float g_B4 [NMAX*4];   // sum of edge softmax (first 4 comps) per src
__device__ float g_xs8[NMAX*8];   // x @ w_weight[:, :128]^T + w_bias (padded)
__device__ float g_xd8[NMAX*8];   // x @ w_weight[:, 128:]^T (padded)
__device__ float g_aw8[NMAX*8];   // node attention softmax weights (padded)
__device__ float g_h  [NMAX*HH];  // relu(topo @ t1_w^T + t1_b)
__device__ int   g_deg[NMAX];
__device__ int   g_degmax;
__device__ int   g_is64;

// ---------------- Threefry-2x32 (JAX partitionable semantics) ----------------
__host__ __device__ constexpr unsigned rotl32(unsigned v, int s) {
    return (v << s) | (v >> (32 - s));
}
struct TFout { unsigned a, b; };
__host__ __device__ constexpr TFout tf2x32(unsigned k0, unsigned k1,
                                           unsigned x0, unsigned x1) {
    unsigned ks[3] = {k0, k1, k0 ^ k1 ^ 0x1BD11BDAu};
    const int R0[4] = {13, 15, 26, 6};
    const int R1[4] = {17, 29, 16, 24};
    x0 += ks[0]; x1 += ks[1];
    for (int i = 0; i < 5; i++) {
        for (int j = 0; j < 4; j++) {
            int r = (i % 2 == 0) ? R0[j] : R1[j];
            x0 += x1; x1 = rotl32(x1, r); x1 ^= x0;
        }
        x0 += ks[(i + 1) % 3];
        x1 += ks[(i + 2) % 3] + (unsigned)(i + 1);
    }
    return {x0, x1};
}
// split(key(42)) foldlike: key_i = threefry(key, hi=0, lo=i), both words
constexpr TFout KEY1 = tf2x32(0u, 42u, 0u, 0u);
constexpr TFout KEY2 = tf2x32(0u, 42u, 0u, 1u);

__device__ __forceinline__ float jax_uniform01(unsigned key0, unsigned key1,
                                               unsigned n) {
    TFout r = tf2x32(key0, key1, 0u, n);
    unsigned bits = r.a ^ r.b;
    return __uint_as_float(0x3F800000u | (bits >> 9)) - 1.0f;
}

// ---------------- edge index loader (int32/int64 runtime-detected) ----------
__device__ __forceinline__ int ld_edge(const void* ei, long long pos, int is64) {
    return is64 ? (int)__ldg(((const long long*)ei) + pos)
                : __ldg(((const int*)ei) + pos);
}

// ---------------- K0: zero scratch + detect index dtype ---------------------
__global__ void k_init(const int* ei32, long long n_elems, int N) {
    long long i = (long long)blockIdx.x * blockDim.x + threadIdx.x;
    if (i < (long long)N * 4) g_B4[i] = 0.0f;
    if (i < N)                g_deg[i] = 0;
    if (i == 0) {
        g_degmax = 0;
        long long cnt = n_elems / 2; if (cnt > 64) cnt = 64;
        int orv = 0;
        for (long long t = 0; t < cnt; t++) orv |= ei32[2 * t + 1];
        g_is64 = (orv == 0) ? 1 : 0;
    }
}

// ---------------- K1: degree histogram over src -------------------------------
__global__ void k_degree(const void* ei, long long E) {
    long long e = (long long)blockIdx.x * blockDim.x + threadIdx.x;
    if (e >= E) return;
    int s = ld_edge(ei, e, g_is64);
    atomicAdd(&g_deg[s], 1);
}

// ---------------- K2: max(degree) ---------------------------------------------
__global__ void k_degmax(int N) {
    int v = 0;
    for (int i = blockIdx.x * blockDim.x + threadIdx.x; i < N;
         i += gridDim.x * blockDim.x)
        v = max(v, g_deg[i]);
    for (int o = 16; o; o >>= 1) v = max(v, __shfl_xor_sync(0xffffffffu, v, o));
    __shared__ int sm[8];
    if ((threadIdx.x & 31) == 0) sm[threadIdx.x >> 5] = v;
    __syncthreads();
    if (threadIdx.x < 8) {
        int t = sm[threadIdx.x];
        for (int o = 4; o; o >>= 1) t = max(t, __shfl_xor_sync(0xffu, t, o));
        if (threadIdx.x == 0) atomicMax(&g_degmax, t);
    }
}

// ---------------- K3: per-node precompute -------------------------------------
// Warp owns 8 nodes; 4 threads per node (quarter-columns). x rows staged
// through smem coalesced (quarters padded to 36 floats = 144B, 16B-aligned,
// conflict-free); 2-step shfl_xor reduction.
#define QPAD 36
#define RPAD 144
__global__ void __launch_bounds__(256)
k_nodeA(const float* __restrict__ x,
        const float* __restrict__ attn_w, const float* __restrict__ attn_b,
        const float* __restrict__ w_w,  const float* __restrict__ w_b,
        const float* __restrict__ t1w,  const float* __restrict__ t1b,
        int N, float Ef) {
    __shared__ float  s_x[8][8 * RPAD];  // per-warp: 8 rows x (4 quarters x 36)
    __shared__ float4 s_attn[AA * 32];   // [5][128]
    __shared__ float4 s_w[AA * 64];      // [5][256]
    __shared__ float4 s_t1wT[AA * 16];   // transposed [5][64]
    __shared__ float4 s_t1b4[16];
    __shared__ float  s_ab[AA], s_wb[AA];
    int tid = threadIdx.x;
    for (int i = tid; i < AA * 32; i += 256) s_attn[i] = ((const float4*)attn_w)[i];
    for (int i = tid; i < AA * 64; i += 256) s_w[i]    = ((const float4*)w_w)[i];
    for (int idx = tid; idx < AA * HH; idx += 256) {
        int i = idx / HH, j = idx % HH;                // t1w is [64][5]
        ((float*)s_t1wT)[i * HH + j] = t1w[j * AA + i];
    }
    for (int i = tid; i < 16; i += 256) s_t1b4[i] = ((const float4*)t1b)[i];
    if (tid < AA) { s_ab[tid] = attn_b[tid]; s_wb[tid] = w_b[tid]; }
    __syncthreads();

    int warp = tid >> 5, lane = tid & 31;
    int wbase = blockIdx.x * 64 + warp * 8;
    float* buf = s_x[warp];

    // ---- stage 8 rows, coalesced; lane l -> quarter (l>>3), slot (l&7) ----
    int soff = (lane >> 3) * QPAD + (lane & 7) * 4;
#pragma unroll
    for (int r = 0; r < 8; r++) {
        int n = wbase + r;
        float4 v = make_float4(0.f, 0.f, 0.f, 0.f);
        if (n < N) v = __ldg(((const float4*)x) + (size_t)n * 32 + lane);
        *(float4*)&buf[r * RPAD + soff] = v;
    }
    __syncwarp();

    int r = lane >> 2, q = lane & 3;
    int n = wbase + r;

    float pa[AA], ps[AA], pd[AA];
#pragma unroll
    for (int k = 0; k < AA; k++) { pa[k] = 0.f; ps[k] = 0.f; pd[k] = 0.f; }

    const float4* xq = (const float4*)&buf[r * RPAD + q * QPAD];
#pragma unroll
    for (int j = 0; j < 8; j++) {
        float4 xv = xq[j];
        int c = q * 8 + j;          // global float4 column 0..31
#pragma unroll
        for (int k = 0; k < AA; k++) {
            float4 av = s_attn[k * 32 + c];
            pa[k] += xv.x * av.x + xv.y * av.y + xv.z * av.z + xv.w * av.w;
            float4 sv = s_w[k * 64 + c];
            ps[k] += xv.x * sv.x + xv.y * sv.y + xv.z * sv.z + xv.w * sv.w;
            float4 dv = s_w[k * 64 + 32 + c];
            pd[k] += xv.x * dv.x + xv.y * dv.y + xv.z * dv.z + xv.w * dv.w;
        }
    }
    // ---- reduce across the 4 quarter-threads (all lanes get totals) ----
#pragma unroll
    for (int k = 0; k < AA; k++) {
        pa[k] += __shfl_xor_sync(0xffffffffu, pa[k], 1);
        pa[k] += __shfl_xor_sync(0xffffffffu, pa[k], 2);
        ps[k] += __shfl_xor_sync(0xffffffffu, ps[k], 1);
        ps[k] += __shfl_xor_sync(0xffffffffu, ps[k], 2);
        pd[k] += __shfl_xor_sync(0xffffffffu, pd[k], 1);
        pd[k] += __shfl_xor_sync(0xffffffffu, pd[k], 2);
    }
#pragma unroll
    for (int k = 0; k < AA; k++) { pa[k] += s_ab[k]; ps[k] += s_wb[k]; }

    // attention softmax (redundant in 4 lanes; trivial)
    float m = pa[0];
#pragma unroll
    for (int k = 1; k < AA; k++) m = fmaxf(m, pa[k]);
    float ev[AA], sum = 0.f;
#pragma unroll
    for (int k = 0; k < AA; k++) { ev[k] = __expf(pa[k] - m); sum += ev[k]; }
    float inv = __fdividef(1.0f, sum);

    if (n < N) {
        if (q == 0) {
            *(float4*)(g_aw8 + (size_t)n * 8) =
                make_float4(ev[0]*inv, ev[1]*inv, ev[2]*inv, ev[3]*inv);
            g_aw8[(size_t)n * 8 + 4] = ev[4] * inv;
        } else if (q == 1) {
            *(float4*)(g_xs8 + (size_t)n * 8) =
                make_float4(ps[0], ps[1], ps[2], ps[3]);
            g_xs8[(size_t)n * 8 + 4] = ps[4];
        } else if (q == 2) {
            *(float4*)(g_xd8 + (size_t)n * 8) =
                make_float4(pd[0], pd[1], pd[2], pd[3]);
            g_xd8[(size_t)n * 8 + 4] = pd[4];
        }
    }

    // ---- topology features + hidden layer ----
    float deg = (n < N) ? (float)__ldg(&g_deg[n]) : 0.f;
    // one threefry per lane; q parity selects key, then exchange
    unsigned kk0 = (q & 1) ? KEY2.a : KEY1.a;
    unsigned kk1 = (q & 1) ? KEY2.b : KEY1.b;
    float u = jax_uniform01(kk0, kk1, (unsigned)n);
    int qb = lane & ~3;
    float u0 = __shfl_sync(0xffffffffu, u, qb + 0);
    float u1 = __shfl_sync(0xffffffffu, u, qb + 1);

    float dmaxf = (float)g_degmax;
    float meanf = Ef / (float)N;
    float tv[5];
    tv[0] = deg / (dmaxf + 1e-6f);
    tv[1] = u0 * 0.5f + 0.25f;
    tv[2] = deg / (Ef + 1e-6f);
    tv[3] = 1.0f / (1.0f + __expf(-(deg - meanf)));
    tv[4] = u1;

    if (n < N) {
        float4* hout = (float4*)g_h;
#pragma unroll
        for (int jc = 0; jc < 4; jc++) {
            int jc4 = q * 4 + jc;
            float4 hv = s_t1b4[jc4];
#pragma unroll
            for (int i = 0; i < AA; i++) {
                float4 wv = s_t1wT[i * 16 + jc4];
                hv.x += tv[i] * wv.x; hv.y += tv[i] * wv.y;
                hv.z += tv[i] * wv.z; hv.w += tv[i] * wv.w;
            }
            hv.x = fmaxf(hv.x, 0.f); hv.y = fmaxf(hv.y, 0.f);
            hv.z = fmaxf(hv.z, 0.f); hv.w = fmaxf(hv.w, 0.f);
            hout[(size_t)n * 16 + jc4] = hv;
        }
    }
}

// ---------------- K4: edge kernel — thread-per-edge softmax, warp store ------
__global__ void __launch_bounds__(256)
k_edge(const void* __restrict__ ei, long long E,
       const float* __restrict__ anchor, float* __restrict__ outE) {
    __shared__ float4 s_b4[256];
    __shared__ float  s_b1[256];
    int tid  = threadIdx.x;
    int lane = tid & 31;
    int warp = tid >> 5;
    int is64 = g_is64;

    // anchor columns 4*lane..4*lane+3 register-resident
    float4 a0 = __ldg(((const float4*)anchor) + 0 * 32 + lane);
    float4 a1 = __ldg(((const float4*)anchor) + 1 * 32 + lane);
    float4 a2 = __ldg(((const float4*)anchor) + 2 * 32 + lane);
    float4 a3 = __ldg(((const float4*)anchor) + 3 * 32 + lane);
    float4 a4 = __ldg(((const float4*)anchor) + 4 * 32 + lane);

    long long e = (long long)blockIdx.x * 256 + tid;
    if (e < E) {
        int src = ld_edge(ei, e, is64);
        int dst = ld_edge(ei, E + e, is64);
        float4 s4 = __ldg((const float4*)(g_xs8 + (size_t)src * 8));
        float  s5 = __ldg(g_xs8 + (size_t)src * 8 + 4);
        float4 d4 = __ldg((const float4*)(g_xd8 + (size_t)dst * 8));
        float  d5 = __ldg(g_xd8 + (size_t)dst * 8 + 4);
        float l[5];
        l[0] = s4.x + d4.x; l[1] = s4.y + d4.y; l[2] = s4.z + d4.z;
        l[3] = s4.w + d4.w; l[4] = s5 + d5;
#pragma unroll
        for (int k = 0; k < 5; k++) l[k] = fmaxf(l[k], 0.01f * l[k]); // leaky
        float m = l[0];
#pragma unroll
        for (int k = 1; k < 5; k++) m = fmaxf(m, l[k]);
        float ev[5], sum = 0.f;
#pragma unroll
        for (int k = 0; k < 5; k++) { ev[k] = __expf(l[k] - m); sum += ev[k]; }
        float inv = __fdividef(1.0f, sum);
        float b0 = ev[0]*inv, b1 = ev[1]*inv, b2 = ev[2]*inv,
              b3 = ev[3]*inv, b4 = ev[4]*inv;
        // scatter first 4 components; 5th derived in k_final from degree
        atomicAdd(&g_B4[(size_t)src * 4 + 0], b0);
        atomicAdd(&g_B4[(size_t)src * 4 + 1], b1);
        atomicAdd(&g_B4[(size_t)src * 4 + 2], b2);
        atomicAdd(&g_B4[(size_t)src * 4 + 3], b3);
        s_b4[tid] = make_float4(b0, b1, b2, b3);
        s_b1[tid] = b4;
    }
    __syncwarp();

    long long base = (long long)blockIdx.x * 256 + warp * 32;
    float4* o4 = (float4*)outE;
#pragma unroll 4
    for (int j = 0; j < 32; j++) {
        long long eid = base + j;
        if (eid >= E) break;
        int sb = warp * 32 + j;                  // uniform -> broadcast LDS
        float4 bb = s_b4[sb];
        float  b4v = s_b1[sb];
        float4 o;
        o.x = bb.x*a0.x + bb.y*a1.x + bb.z*a2.x + bb.w*a3.x + b4v*a4.x;
        o.y = bb.x*a0.y + bb.y*a1.y + bb.z*a2.y + bb.w*a3.y + b4v*a4.y;
        o.z = bb.x*a0.z + bb.y*a1.z + bb.z*a2.z + bb.w*a3.z + b4v*a4.z;
        o.w = bb.x*a0.w + bb.y*a1.w + bb.z*a2.w + bb.w*a3.w + b4v*a4.w;
        __stcs(o4 + (size_t)eid * 32 + lane, o);  // streaming store
    }
}

// ---------------- K5: final per-node (thread owns one output column) ---------
__global__ void __launch_bounds__(256, 2)
k_final(const float* __restrict__ x,
        const float* __restrict__ node_anchor, const float* __restrict__ anchor,
        const float* __restrict__ t2w, const float* __restrict__ t2b,
        float* __restrict__ outF, int N) {
    int lane = threadIdx.x & 31;
    int gw = (int)((blockIdx.x * blockDim.x + threadIdx.x) >> 5);
    int stream = gw >> 2;
    int cg = gw & 3;
    int nStreams = (int)((gridDim.x * blockDim.x) >> 7);
    int col = cg * 32 + lane;

    float wreg[HH];
#pragma unroll
    for (int j4 = 0; j4 < 16; j4++) {
        float4 wv = ((const float4*)t2w)[(size_t)col * 16 + j4];
        wreg[4*j4+0] = wv.x; wreg[4*j4+1] = wv.y;
        wreg[4*j4+2] = wv.z; wreg[4*j4+3] = wv.w;
    }
    float areg[AA], nareg[AA];
#pragma unroll
    for (int k = 0; k < AA; k++) {
        areg[k]  = __ldg(&anchor[k * DD + col]);
        nareg[k] = __ldg(&node_anchor[k * DD + col]);
    }
    float bias = __ldg(&t2b[col]);

    for (int n = stream; n < N; n += nStreams) {
        float acc = bias;
        const float4* h4 = (const float4*)(g_h + (size_t)n * HH);
#pragma unroll
        for (int j4 = 0; j4 < 16; j4++) {
            float4 hv = h4[j4];      // uniform address -> broadcast
            acc += hv.x * wreg[4*j4+0] + hv.y * wreg[4*j4+1]
                 + hv.z * wreg[4*j4+2] + hv.w * wreg[4*j4+3];
        }
        float4 B   = *(const float4*)(g_B4 + (size_t)n * 4);
        float deg  = (float)g_deg[n];
        float B4v  = deg - B.x - B.y - B.z - B.w;
        float agg  = B.x*areg[0] + B.y*areg[1] + B.z*areg[2] + B.w*areg[3]
                   + B4v*areg[4];
        float4 aw4 = *(const float4*)(g_aw8 + (size_t)n * 8);
        float aw5  = g_aw8[(size_t)n * 8 + 4];
        float np   = aw4.x*nareg[0] + aw4.y*nareg[1] + aw4.z*nareg[2]
                   + aw4.w*nareg[3] + aw5*nareg[4];
        float xv = x[(size_t)n * DD + col];
        outF[(size_t)n * DD + col] = xv + np + acc * agg;
    }
}

// ---------------- launch ------------------------------------------------------
extern "C" void kernel_launch(void* const* d_in, const int* in_sizes, int n_in,
                              void* d_out, int out_size) {
    const float* x           = (const float*)d_in[0];
    const void*  ei          = d_in[1];
    const float* anchor      = (const float*)d_in[3];
    const float* w_w         = (const float*)d_in[4];
    const float* w_b         = (const float*)d_in[5];
    const float* node_anchor = (const float*)d_in[6];
    const float* attn_w      = (const float*)d_in[7];
    const float* attn_b      = (const float*)d_in[8];
    const float* t1w         = (const float*)d_in[9];
    const float* t1b         = (const float*)d_in[10];
    const float* t2w         = (const float*)d_in[11];
    const float* t2b         = (const float*)d_in[12];

    int       N  = in_sizes[0] / DD;
    long long E  = (long long)in_sizes[1] / 2;
    float     Ef = (float)E;

    float* outF = (float*)d_out;                  // final_x [N, D]
    float* outE = outF + (size_t)N * DD;          // edge_prompt [E, D]

    k_init  <<<(N * 4 + 255) / 256, 256>>>((const int*)ei,
                                           (long long)in_sizes[1], N);
    k_degree<<<(unsigned)((E + 255) / 256), 256>>>(ei, E);
    k_degmax<<<128, 256>>>(N);
    k_nodeA <<<(N + 63) / 64, 256>>>(x, attn_w, attn_b, w_w, w_b,
                                     t1w, t1b, N, Ef);
    k_edge  <<<(unsigned)((E + 255) / 256), 256>>>(ei, E, anchor, outE);
    k_final <<<592, 256>>>(x, node_anchor, anchor, t2w, t2b, outF, N);
}

// round 6
// speedup vs baseline: 1.2418x; 1.2418x over previous
#include <cuda_runtime.h>
#include <cstdint>
#include <cstddef>

// Problem constants (reference: N=50000, D=128, E=800000, A=5)
#define NMAX 50000
#define DD 128
#define AA 5
#define HH 64
#define BN 128   // nodes per block in k_nodeA

// ---------------- scratch (static device globals) ----------------------------
__device__ float g_B4 [NMAX*4];   // sum of edge softmax (first 4 comps) per src
__device__ float g_xs8[NMAX*8];   // x @ w_weight[:, :128]^T + w_bias (padded)
__device__ float g_xd8[NMAX*8];   // x @ w_weight[:, 128:]^T (padded)
__device__ float g_aw8[NMAX*8];   // node attention softmax weights (padded)
__device__ float g_h  [NMAX*HH];  // relu(topo @ t1_w^T + t1_b)
__device__ int   g_deg[NMAX];
__device__ int   g_degmax;
__device__ int   g_is64;

// ---------------- f32x2 packed math helpers ----------------------------------
__device__ __forceinline__ unsigned long long pack2(float v) {
    unsigned long long r;
    asm("mov.b64 %0, {%1, %1};" : "=l"(r) : "f"(v));
    return r;
}
__device__ __forceinline__ unsigned long long packf2(float x, float y) {
    unsigned long long r;
    asm("mov.b64 %0, {%1, %2};" : "=l"(r) : "f"(x), "f"(y));
    return r;
}
__device__ __forceinline__ unsigned long long mul2(unsigned long long a,
                                                   unsigned long long b) {
    unsigned long long d;
    asm("mul.rn.f32x2 %0, %1, %2;" : "=l"(d) : "l"(a), "l"(b));
    return d;
}
__device__ __forceinline__ unsigned long long fma2(unsigned long long a,
                                                   unsigned long long b,
                                                   unsigned long long c) {
    unsigned long long d;
    asm("fma.rn.f32x2 %0, %1, %2, %3;" : "=l"(d) : "l"(a), "l"(b), "l"(c));
    return d;
}
__device__ __forceinline__ void unpack2(unsigned long long v, float& x, float& y) {
    asm("mov.b64 {%0, %1}, %2;" : "=f"(x), "=f"(y) : "l"(v));
}

// ---------------- Threefry-2x32 (JAX partitionable semantics) ----------------
__host__ __device__ constexpr unsigned rotl32(unsigned v, int s) {
    return (v << s) | (v >> (32 - s));
}
struct TFout { unsigned a, b; };
__host__ __device__ constexpr TFout tf2x32(unsigned k0, unsigned k1,
                                           unsigned x0, unsigned x1) {
    unsigned ks[3] = {k0, k1, k0 ^ k1 ^ 0x1BD11BDAu};
    const int R0[4] = {13, 15, 26, 6};
    const int R1[4] = {17, 29, 16, 24};
    x0 += ks[0]; x1 += ks[1];
    for (int i = 0; i < 5; i++) {
        for (int j = 0; j < 4; j++) {
            int r = (i % 2 == 0) ? R0[j] : R1[j];
            x0 += x1; x1 = rotl32(x1, r); x1 ^= x0;
        }
        x0 += ks[(i + 1) % 3];
        x1 += ks[(i + 2) % 3] + (unsigned)(i + 1);
    }
    return {x0, x1};
}
// split(key(42)) foldlike: key_i = threefry(key, hi=0, lo=i), both words
constexpr TFout KEY1 = tf2x32(0u, 42u, 0u, 0u);
constexpr TFout KEY2 = tf2x32(0u, 42u, 0u, 1u);

__device__ __forceinline__ float jax_uniform01(unsigned key0, unsigned key1,
                                               unsigned n) {
    TFout r = tf2x32(key0, key1, 0u, n);
    unsigned bits = r.a ^ r.b;
    return __uint_as_float(0x3F800000u | (bits >> 9)) - 1.0f;
}

// ---------------- edge index loader (int32/int64 runtime-detected) ----------
__device__ __forceinline__ int ld_edge(const void* ei, long long pos, int is64) {
    return is64 ? (int)__ldg(((const long long*)ei) + pos)
                : __ldg(((const int*)ei) + pos);
}

// ---------------- K0: zero scratch + detect index dtype ---------------------
__global__ void k_init(const int* ei32, long long n_elems, int N) {
    long long i = (long long)blockIdx.x * blockDim.x + threadIdx.x;
    if (i < (long long)N * 4) g_B4[i] = 0.0f;
    if (i < N)                g_deg[i] = 0;
    if (i == 0) {
        g_degmax = 0;
        long long cnt = n_elems / 2; if (cnt > 64) cnt = 64;
        int orv = 0;
        for (long long t = 0; t < cnt; t++) orv |= ei32[2 * t + 1];
        g_is64 = (orv == 0) ? 1 : 0;
    }
}

// ---------------- K1: degree histogram over src -------------------------------
__global__ void k_degree(const void* ei, long long E) {
    long long e = (long long)blockIdx.x * blockDim.x + threadIdx.x;
    if (e >= E) return;
    int s = ld_edge(ei, e, g_is64);
    atomicAdd(&g_deg[s], 1);
}

// ---------------- K2: max(degree) ---------------------------------------------
__global__ void k_degmax(int N) {
    int v = 0;
    for (int i = blockIdx.x * blockDim.x + threadIdx.x; i < N;
         i += gridDim.x * blockDim.x)
        v = max(v, g_deg[i]);
    for (int o = 16; o; o >>= 1) v = max(v, __shfl_xor_sync(0xffffffffu, v, o));
    __shared__ int sm[8];
    if ((threadIdx.x & 31) == 0) sm[threadIdx.x >> 5] = v;
    __syncthreads();
    if (threadIdx.x < 8) {
        int t = sm[threadIdx.x];
        for (int o = 4; o; o >>= 1) t = max(t, __shfl_xor_sync(0xffu, t, o));
        if (threadIdx.x == 0) atomicMax(&g_degmax, t);
    }
}

// ---------------- K3: per-node precompute (thread per node, staged x) --------
// Weights in smem read UNIFORMLY (broadcast, conflict-free). x rows staged
// per column-chunk through smem: coalesced LDG, conflict-free STS/LDS
// (row stride 33 words).
__global__ void __launch_bounds__(BN)
k_nodeA(const float* __restrict__ x,
        const float* __restrict__ attn_w, const float* __restrict__ attn_b,
        const float* __restrict__ w_w,  const float* __restrict__ w_b,
        const float* __restrict__ t1w,  const float* __restrict__ t1b,
        int N, float Ef) {
    __shared__ float  s_x[BN * 33];      // 16.9 KB, conflict-free layout
    __shared__ float4 s_attn[AA * 32];   // [5][128]
    __shared__ float4 s_w[AA * 64];      // [5][256]
    __shared__ float4 s_t1wT[AA * 16];   // transposed [5][64]
    __shared__ float4 s_t1b4[16];
    __shared__ float  s_ab[AA], s_wb[AA];
    int tid = threadIdx.x;
    for (int i = tid; i < AA * 32; i += BN) s_attn[i] = ((const float4*)attn_w)[i];
    for (int i = tid; i < AA * 64; i += BN) s_w[i]    = ((const float4*)w_w)[i];
    for (int idx = tid; idx < AA * HH; idx += BN) {
        int i = idx / HH, j = idx % HH;                // t1w is [64][5]
        ((float*)s_t1wT)[i * HH + j] = t1w[j * AA + i];
    }
    for (int i = tid; i < 16; i += BN) s_t1b4[i] = ((const float4*)t1b)[i];
    if (tid < AA) { s_ab[tid] = attn_b[tid]; s_wb[tid] = w_b[tid]; }
    __syncthreads();

    int nbase = blockIdx.x * BN;
    int n = nbase + tid;

    float pa[AA], ps[AA], pd[AA];
#pragma unroll
    for (int k = 0; k < AA; k++) { pa[k] = 0.f; ps[k] = 0.f; pd[k] = 0.f; }

    const float4* xg = (const float4*)x;
#pragma unroll
    for (int ch = 0; ch < 4; ch++) {
        if (ch) __syncthreads();
        // stage BN rows x 8 float4 (this chunk), coalesced
#pragma unroll
        for (int it = 0; it < 8; it++) {
            int idx = it * BN + tid;
            int r = idx >> 3, c = idx & 7;
            int gn = nbase + r;
            float4 v = make_float4(0.f, 0.f, 0.f, 0.f);
            if (gn < N) v = __ldg(xg + (size_t)gn * 32 + ch * 8 + c);
            float* p = s_x + r * 33 + c * 4;
            p[0] = v.x; p[1] = v.y; p[2] = v.z; p[3] = v.w;
        }
        __syncthreads();
        const float* xr = s_x + tid * 33;
#pragma unroll
        for (int j4 = 0; j4 < 8; j4++) {
            float x0 = xr[j4*4+0], x1 = xr[j4*4+1];
            float x2 = xr[j4*4+2], x3 = xr[j4*4+3];
            int c = ch * 8 + j4;
#pragma unroll
            for (int k = 0; k < AA; k++) {
                float4 av = s_attn[k * 32 + c];
                pa[k] += x0*av.x + x1*av.y + x2*av.z + x3*av.w;
                float4 sv = s_w[k * 64 + c];
                ps[k] += x0*sv.x + x1*sv.y + x2*sv.z + x3*sv.w;
                float4 dv = s_w[k * 64 + 32 + c];
                pd[k] += x0*dv.x + x1*dv.y + x2*dv.z + x3*dv.w;
            }
        }
    }
    if (n >= N) return;

#pragma unroll
    for (int k = 0; k < AA; k++) { pa[k] += s_ab[k]; ps[k] += s_wb[k]; }

    // attention softmax (per-thread registers)
    float m = pa[0];
#pragma unroll
    for (int k = 1; k < AA; k++) m = fmaxf(m, pa[k]);
    float ev[AA], sum = 0.f;
#pragma unroll
    for (int k = 0; k < AA; k++) { ev[k] = __expf(pa[k] - m); sum += ev[k]; }
    float inv = __fdividef(1.0f, sum);

    *(float4*)(g_aw8 + (size_t)n * 8) =
        make_float4(ev[0]*inv, ev[1]*inv, ev[2]*inv, ev[3]*inv);
    g_aw8[(size_t)n * 8 + 4] = ev[4] * inv;
    *(float4*)(g_xs8 + (size_t)n * 8) = make_float4(ps[0], ps[1], ps[2], ps[3]);
    g_xs8[(size_t)n * 8 + 4] = ps[4];
    *(float4*)(g_xd8 + (size_t)n * 8) = make_float4(pd[0], pd[1], pd[2], pd[3]);
    g_xd8[(size_t)n * 8 + 4] = pd[4];

    // topology features + hidden layer (per-thread)
    float deg   = (float)__ldg(&g_deg[n]);
    float dmaxf = (float)g_degmax;
    float meanf = Ef / (float)N;
    float tv[5];
    tv[0] = deg / (dmaxf + 1e-6f);
    tv[1] = jax_uniform01(KEY1.a, KEY1.b, (unsigned)n) * 0.5f + 0.25f;
    tv[2] = deg / (Ef + 1e-6f);
    tv[3] = 1.0f / (1.0f + __expf(-(deg - meanf)));
    tv[4] = jax_uniform01(KEY2.a, KEY2.b, (unsigned)n);

    float4* hout = (float4*)(g_h + (size_t)n * HH);
#pragma unroll
    for (int jc = 0; jc < 16; jc++) {
        float4 hv = s_t1b4[jc];
#pragma unroll
        for (int i = 0; i < AA; i++) {
            float4 wv = s_t1wT[i * 16 + jc];
            hv.x += tv[i] * wv.x; hv.y += tv[i] * wv.y;
            hv.z += tv[i] * wv.z; hv.w += tv[i] * wv.w;
        }
        hv.x = fmaxf(hv.x, 0.f); hv.y = fmaxf(hv.y, 0.f);
        hv.z = fmaxf(hv.z, 0.f); hv.w = fmaxf(hv.w, 0.f);
        hout[jc] = hv;
    }
}

// ---------------- K4: edge kernel — thread-per-edge softmax, f32x2 store -----
__global__ void __launch_bounds__(256)
k_edge(const void* __restrict__ ei, long long E,
       const float* __restrict__ anchor, float* __restrict__ outE) {
    __shared__ unsigned long long s_bp[256 * 5];  // packed (b,b) per edge
    int tid  = threadIdx.x;
    int lane = tid & 31;
    int warp = tid >> 5;
    int is64 = g_is64;

    // anchor columns 4*lane..4*lane+3 as packed f32x2 pairs, register-resident
    unsigned long long alo[AA], ahi[AA];
#pragma unroll
    for (int k = 0; k < AA; k++) {
        float4 a = __ldg(((const float4*)anchor) + k * 32 + lane);
        alo[k] = packf2(a.x, a.y);
        ahi[k] = packf2(a.z, a.w);
    }

    long long e = (long long)blockIdx.x * 256 + tid;
    if (e < E) {
        int src = ld_edge(ei, e, is64);
        int dst = ld_edge(ei, E + e, is64);
        float4 s4 = __ldg((const float4*)(g_xs8 + (size_t)src * 8));
        float  s5 = __ldg(g_xs8 + (size_t)src * 8 + 4);
        float4 d4 = __ldg((const float4*)(g_xd8 + (size_t)dst * 8));
        float  d5 = __ldg(g_xd8 + (size_t)dst * 8 + 4);
        float l[5];
        l[0] = s4.x + d4.x; l[1] = s4.y + d4.y; l[2] = s4.z + d4.z;
        l[3] = s4.w + d4.w; l[4] = s5 + d5;
#pragma unroll
        for (int k = 0; k < 5; k++) l[k] = fmaxf(l[k], 0.01f * l[k]); // leaky
        float m = l[0];
#pragma unroll
        for (int k = 1; k < 5; k++) m = fmaxf(m, l[k]);
        float ev[5], sum = 0.f;
#pragma unroll
        for (int k = 0; k < 5; k++) { ev[k] = __expf(l[k] - m); sum += ev[k]; }
        float inv = __fdividef(1.0f, sum);
        float b[5];
#pragma unroll
        for (int k = 0; k < 5; k++) b[k] = ev[k] * inv;
        // scatter first 4 components; 5th derived in k_final from degree
        atomicAdd(&g_B4[(size_t)src * 4 + 0], b[0]);
        atomicAdd(&g_B4[(size_t)src * 4 + 1], b[1]);
        atomicAdd(&g_B4[(size_t)src * 4 + 2], b[2]);
        atomicAdd(&g_B4[(size_t)src * 4 + 3], b[3]);
#pragma unroll
        for (int k = 0; k < 5; k++) s_bp[tid * 5 + k] = pack2(b[k]);
    }
    __syncwarp();

    long long base = (long long)blockIdx.x * 256 + warp * 32;
    float4* o4 = (float4*)outE;
#pragma unroll 4
    for (int j = 0; j < 32; j++) {
        long long eid = base + j;
        if (eid >= E) break;
        const unsigned long long* bp = &s_bp[(warp * 32 + j) * 5]; // uniform
        unsigned long long p0 = bp[0], p1 = bp[1], p2 = bp[2],
                           p3 = bp[3], p4 = bp[4];
        unsigned long long lo = mul2(p0, alo[0]);
        lo = fma2(p1, alo[1], lo); lo = fma2(p2, alo[2], lo);
        lo = fma2(p3, alo[3], lo); lo = fma2(p4, alo[4], lo);
        unsigned long long hi = mul2(p0, ahi[0]);
        hi = fma2(p1, ahi[1], hi); hi = fma2(p2, ahi[2], hi);
        hi = fma2(p3, ahi[3], hi); hi = fma2(p4, ahi[4], hi);
        float4 o;
        unpack2(lo, o.x, o.y);
        unpack2(hi, o.z, o.w);
        __stcs(o4 + (size_t)eid * 32 + lane, o);  // streaming store
    }
}

// ---------------- K5: final per-node (thread owns one output column) ---------
__global__ void __launch_bounds__(256, 2)
k_final(const float* __restrict__ x,
        const float* __restrict__ node_anchor, const float* __restrict__ anchor,
        const float* __restrict__ t2w, const float* __restrict__ t2b,
        float* __restrict__ outF, int N) {
    int lane = threadIdx.x & 31;
    int gw = (int)((blockIdx.x * blockDim.x + threadIdx.x) >> 5);
    int stream = gw >> 2;
    int cg = gw & 3;
    int nStreams = (int)((gridDim.x * blockDim.x) >> 7);
    int col = cg * 32 + lane;

    float wreg[HH];
#pragma unroll
    for (int j4 = 0; j4 < 16; j4++) {
        float4 wv = ((const float4*)t2w)[(size_t)col * 16 + j4];
        wreg[4*j4+0] = wv.x; wreg[4*j4+1] = wv.y;
        wreg[4*j4+2] = wv.z; wreg[4*j4+3] = wv.w;
    }
    float areg[AA], nareg[AA];
#pragma unroll
    for (int k = 0; k < AA; k++) {
        areg[k]  = __ldg(&anchor[k * DD + col]);
        nareg[k] = __ldg(&node_anchor[k * DD + col]);
    }
    float bias = __ldg(&t2b[col]);

    for (int n = stream; n < N; n += nStreams) {
        float acc = bias;
        const float4* h4 = (const float4*)(g_h + (size_t)n * HH);
#pragma unroll
        for (int j4 = 0; j4 < 16; j4++) {
            float4 hv = h4[j4];      // uniform address -> broadcast
            acc += hv.x * wreg[4*j4+0] + hv.y * wreg[4*j4+1]
                 + hv.z * wreg[4*j4+2] + hv.w * wreg[4*j4+3];
        }
        float4 B   = *(const float4*)(g_B4 + (size_t)n * 4);
        float deg  = (float)g_deg[n];
        float B4v  = deg - B.x - B.y - B.z - B.w;
        float agg  = B.x*areg[0] + B.y*areg[1] + B.z*areg[2] + B.w*areg[3]
                   + B4v*areg[4];
        float4 aw4 = *(const float4*)(g_aw8 + (size_t)n * 8);
        float aw5  = g_aw8[(size_t)n * 8 + 4];
        float np   = aw4.x*nareg[0] + aw4.y*nareg[1] + aw4.z*nareg[2]
                   + aw4.w*nareg[3] + aw5*nareg[4];
        float xv = x[(size_t)n * DD + col];
        outF[(size_t)n * DD + col] = xv + np + acc * agg;
    }
}

// ---------------- launch ------------------------------------------------------
extern "C" void kernel_launch(void* const* d_in, const int* in_sizes, int n_in,
                              void* d_out, int out_size) {
    const float* x           = (const float*)d_in[0];
    const void*  ei          = d_in[1];
    const float* anchor      = (const float*)d_in[3];
    const float* w_w         = (const float*)d_in[4];
    const float* w_b         = (const float*)d_in[5];
    const float* node_anchor = (const float*)d_in[6];
    const float* attn_w      = (const float*)d_in[7];
    const float* attn_b      = (const float*)d_in[8];
    const float* t1w         = (const float*)d_in[9];
    const float* t1b         = (const float*)d_in[10];
    const float* t2w         = (const float*)d_in[11];
    const float* t2b         = (const float*)d_in[12];

    int       N  = in_sizes[0] / DD;
    long long E  = (long long)in_sizes[1] / 2;
    float     Ef = (float)E;

    float* outF = (float*)d_out;                  // final_x [N, D]
    float* outE = outF + (size_t)N * DD;          // edge_prompt [E, D]

    k_init  <<<(N * 4 + 255) / 256, 256>>>((const int*)ei,
                                           (long long)in_sizes[1], N);
    k_degree<<<(unsigned)((E + 255) / 256), 256>>>(ei, E);
    k_degmax<<<128, 256>>>(N);
    k_nodeA <<<(N + BN - 1) / BN, BN>>>(x, attn_w, attn_b, w_w, w_b,
                                        t1w, t1b, N, Ef);
    k_edge  <<<(unsigned)((E + 255) / 256), 256>>>(ei, E, anchor, outE);
    k_final <<<592, 256>>>(x, node_anchor, anchor, t2w, t2b, outF, N);
}

// round 7
// speedup vs baseline: 1.2558x; 1.0112x over previous
#include <cuda_runtime.h>
#include <cstdint>
#include <cstddef>

// Problem constants (reference: N=50000, D=128, E=800000, A=5)
#define NMAX 50000
#define DD 128
#define AA 5
#define HH 64
#define BN 128   // nodes per block in k_nodeA
#define NT 256   // threads per block in k_nodeA (2 threads per node)

// ---------------- scratch (static device globals) ----------------------------
__device__ float g_B4 [NMAX*4];   // sum of edge softmax (first 4 comps) per src
__device__ float g_xs8[NMAX*8];   // x @ w_weight[:, :128]^T + w_bias (padded)
__device__ float g_xd8[NMAX*8];   // x @ w_weight[:, 128:]^T (padded)
__device__ float g_aw8[NMAX*8];   // node attention softmax weights (padded)
__device__ float g_h  [NMAX*HH];  // relu(topo @ t1_w^T + t1_b)
__device__ int   g_deg[NMAX];
__device__ int   g_degmax;
__device__ int   g_is64;

// ---------------- f32x2 packed math helpers ----------------------------------
__device__ __forceinline__ unsigned long long pack2(float v) {
    unsigned long long r;
    asm("mov.b64 %0, {%1, %1};" : "=l"(r) : "f"(v));
    return r;
}
__device__ __forceinline__ unsigned long long packf2(float x, float y) {
    unsigned long long r;
    asm("mov.b64 %0, {%1, %2};" : "=l"(r) : "f"(x), "f"(y));
    return r;
}
__device__ __forceinline__ unsigned long long mul2(unsigned long long a,
                                                   unsigned long long b) {
    unsigned long long d;
    asm("mul.rn.f32x2 %0, %1, %2;" : "=l"(d) : "l"(a), "l"(b));
    return d;
}
__device__ __forceinline__ unsigned long long fma2(unsigned long long a,
                                                   unsigned long long b,
                                                   unsigned long long c) {
    unsigned long long d;
    asm("fma.rn.f32x2 %0, %1, %2, %3;" : "=l"(d) : "l"(a), "l"(b), "l"(c));
    return d;
}
__device__ __forceinline__ void unpack2(unsigned long long v, float& x, float& y) {
    asm("mov.b64 {%0, %1}, %2;" : "=f"(x), "=f"(y) : "l"(v));
}

// ---------------- Threefry-2x32 (JAX partitionable semantics) ----------------
__host__ __device__ constexpr unsigned rotl32(unsigned v, int s) {
    return (v << s) | (v >> (32 - s));
}
struct TFout { unsigned a, b; };
__host__ __device__ constexpr TFout tf2x32(unsigned k0, unsigned k1,
                                           unsigned x0, unsigned x1) {
    unsigned ks[3] = {k0, k1, k0 ^ k1 ^ 0x1BD11BDAu};
    const int R0[4] = {13, 15, 26, 6};
    const int R1[4] = {17, 29, 16, 24};
    x0 += ks[0]; x1 += ks[1];
    for (int i = 0; i < 5; i++) {
        for (int j = 0; j < 4; j++) {
            int r = (i % 2 == 0) ? R0[j] : R1[j];
            x0 += x1; x1 = rotl32(x1, r); x1 ^= x0;
        }
        x0 += ks[(i + 1) % 3];
        x1 += ks[(i + 2) % 3] + (unsigned)(i + 1);
    }
    return {x0, x1};
}
// split(key(42)) foldlike: key_i = threefry(key, hi=0, lo=i), both words
constexpr TFout KEY1 = tf2x32(0u, 42u, 0u, 0u);
constexpr TFout KEY2 = tf2x32(0u, 42u, 0u, 1u);

__device__ __forceinline__ float jax_uniform01(unsigned key0, unsigned key1,
                                               unsigned n) {
    TFout r = tf2x32(key0, key1, 0u, n);
    unsigned bits = r.a ^ r.b;
    return __uint_as_float(0x3F800000u | (bits >> 9)) - 1.0f;
}

// ---------------- edge index loader (int32/int64 runtime-detected) ----------
__device__ __forceinline__ int ld_edge(const void* ei, long long pos, int is64) {
    return is64 ? (int)__ldg(((const long long*)ei) + pos)
                : __ldg(((const int*)ei) + pos);
}

// ---------------- K0: zero scratch + detect index dtype ---------------------
__global__ void k_init(const int* ei32, long long n_elems, int N) {
    long long i = (long long)blockIdx.x * blockDim.x + threadIdx.x;
    if (i < (long long)N * 4) g_B4[i] = 0.0f;
    if (i < N)                g_deg[i] = 0;
    if (i == 0) {
        g_degmax = 0;
        long long cnt = n_elems / 2; if (cnt > 64) cnt = 64;
        int orv = 0;
        for (long long t = 0; t < cnt; t++) orv |= ei32[2 * t + 1];
        g_is64 = (orv == 0) ? 1 : 0;
    }
}

// ---------------- K1: degree histogram over src + fused max ------------------
// atomicAdd returns the pre-increment count; (old+1) for the max-degree node's
// final increment equals its degree, and all other candidates are <= it, so
// block-max of (old+1) + one atomicMax per block yields exact max(degree).
__global__ void __launch_bounds__(256)
k_degree(const void* __restrict__ ei, long long E) {
    int tid = threadIdx.x;
    long long e = (long long)blockIdx.x * 256 + tid;
    int cand = 0;
    if (e < E) {
        int s = ld_edge(ei, e, g_is64);
        cand = atomicAdd(&g_deg[s], 1) + 1;
    }
#pragma unroll
    for (int o = 16; o; o >>= 1)
        cand = max(cand, __shfl_xor_sync(0xffffffffu, cand, o));
    __shared__ int sm[8];
    if ((tid & 31) == 0) sm[tid >> 5] = cand;
    __syncthreads();
    if (tid < 8) {
        int t = sm[tid];
#pragma unroll
        for (int o = 4; o; o >>= 1) t = max(t, __shfl_xor_sync(0xffu, t, o));
        if (tid == 0) atomicMax(&g_degmax, t);
    }
}

// ---------------- K2: per-node precompute (2 threads per node) ----------------
// 256 threads, 128 nodes/block. Thread handles half the columns of one node;
// weight reads are 2-address dual-broadcast (addresses 16 banks apart),
// x staged coalesced into conflict-free smem; one shfl_xor(1) reduction.
__global__ void __launch_bounds__(NT)
k_nodeA(const float* __restrict__ x,
        const float* __restrict__ attn_w, const float* __restrict__ attn_b,
        const float* __restrict__ w_w,  const float* __restrict__ w_b,
        const float* __restrict__ t1w,  const float* __restrict__ t1b,
        int N, float Ef) {
    __shared__ float  s_x[BN * 33];      // 16.9 KB, conflict-free layout
    __shared__ float4 s_attn[AA * 32];   // [5][128]
    __shared__ float4 s_w[AA * 64];      // [5][256]
    __shared__ float4 s_t1wT[AA * 16];   // transposed [5][64]
    __shared__ float4 s_t1b4[16];
    __shared__ float  s_ab[AA], s_wb[AA];
    int tid = threadIdx.x;
    for (int i = tid; i < AA * 32; i += NT) s_attn[i] = ((const float4*)attn_w)[i];
    for (int i = tid; i < AA * 64; i += NT) s_w[i]    = ((const float4*)w_w)[i];
    for (int idx = tid; idx < AA * HH; idx += NT) {
        int i = idx / HH, j = idx % HH;                // t1w is [64][5]
        ((float*)s_t1wT)[i * HH + j] = t1w[j * AA + i];
    }
    for (int i = tid; i < 16; i += NT) s_t1b4[i] = ((const float4*)t1b)[i];
    if (tid < AA) { s_ab[tid] = attn_b[tid]; s_wb[tid] = w_b[tid]; }
    __syncthreads();

    int nbase = blockIdx.x * BN;
    int r = tid >> 1, h = tid & 1;
    int n = nbase + r;

    float pa[AA], ps[AA], pd[AA];
#pragma unroll
    for (int k = 0; k < AA; k++) { pa[k] = 0.f; ps[k] = 0.f; pd[k] = 0.f; }

    const float4* xg = (const float4*)x;
#pragma unroll
    for (int ch = 0; ch < 4; ch++) {
        if (ch) __syncthreads();
        // stage BN rows x 8 float4 (this chunk), coalesced: 4 f4 per thread
#pragma unroll
        for (int it = 0; it < 4; it++) {
            int idx = it * NT + tid;
            int rr = idx >> 3, c = idx & 7;
            int gn = nbase + rr;
            float4 v = make_float4(0.f, 0.f, 0.f, 0.f);
            if (gn < N) v = __ldg(xg + (size_t)gn * 32 + ch * 8 + c);
            float* p = s_x + rr * 33 + c * 4;
            p[0] = v.x; p[1] = v.y; p[2] = v.z; p[3] = v.w;
        }
        __syncthreads();
        const float* xr = s_x + r * 33 + h * 16;
#pragma unroll
        for (int j = 0; j < 4; j++) {
            float x0 = xr[j*4+0], x1 = xr[j*4+1];
            float x2 = xr[j*4+2], x3 = xr[j*4+3];
            int c = ch * 8 + h * 4 + j;   // halves 16 banks apart: dual-bcast
#pragma unroll
            for (int k = 0; k < AA; k++) {
                float4 av = s_attn[k * 32 + c];
                pa[k] += x0*av.x + x1*av.y + x2*av.z + x3*av.w;
                float4 sv = s_w[k * 64 + c];
                ps[k] += x0*sv.x + x1*sv.y + x2*sv.z + x3*sv.w;
                float4 dv = s_w[k * 64 + 32 + c];
                pd[k] += x0*dv.x + x1*dv.y + x2*dv.z + x3*dv.w;
            }
        }
    }
    // reduce the two half-threads (both get totals)
#pragma unroll
    for (int k = 0; k < AA; k++) {
        pa[k] += __shfl_xor_sync(0xffffffffu, pa[k], 1);
        ps[k] += __shfl_xor_sync(0xffffffffu, ps[k], 1);
        pd[k] += __shfl_xor_sync(0xffffffffu, pd[k], 1);
    }
#pragma unroll
    for (int k = 0; k < AA; k++) { pa[k] += s_ab[k]; ps[k] += s_wb[k]; }

    // attention softmax (registers; redundant in both halves)
    float m = pa[0];
#pragma unroll
    for (int k = 1; k < AA; k++) m = fmaxf(m, pa[k]);
    float ev[AA], sum = 0.f;
#pragma unroll
    for (int k = 0; k < AA; k++) { ev[k] = __expf(pa[k] - m); sum += ev[k]; }
    float inv = __fdividef(1.0f, sum);

    bool ok = (n < N);
    if (ok && h == 0) {
        *(float4*)(g_aw8 + (size_t)n * 8) =
            make_float4(ev[0]*inv, ev[1]*inv, ev[2]*inv, ev[3]*inv);
        g_aw8[(size_t)n * 8 + 4] = ev[4] * inv;
        *(float4*)(g_xs8 + (size_t)n * 8) = make_float4(ps[0], ps[1], ps[2], ps[3]);
        g_xs8[(size_t)n * 8 + 4] = ps[4];
    }
    if (ok && h == 1) {
        *(float4*)(g_xd8 + (size_t)n * 8) = make_float4(pd[0], pd[1], pd[2], pd[3]);
        g_xd8[(size_t)n * 8 + 4] = pd[4];
    }

    // topology features + hidden layer
    int nc = (n < N) ? n : (N - 1);
    float deg   = (float)__ldg(&g_deg[nc]);
    float dmaxf = (float)g_degmax;
    float meanf = Ef / (float)N;
    // each half computes one uniform; exchange
    unsigned kk0 = h ? KEY2.a : KEY1.a;
    unsigned kk1 = h ? KEY2.b : KEY1.b;
    float u_own   = jax_uniform01(kk0, kk1, (unsigned)n);
    float u_other = __shfl_xor_sync(0xffffffffu, u_own, 1);
    float u1 = h ? u_other : u_own;   // KEY1 stream
    float u2 = h ? u_own   : u_other; // KEY2 stream

    float tv[5];
    tv[0] = deg / (dmaxf + 1e-6f);
    tv[1] = u1 * 0.5f + 0.25f;
    tv[2] = deg / (Ef + 1e-6f);
    tv[3] = 1.0f / (1.0f + __expf(-(deg - meanf)));
    tv[4] = u2;

    if (ok) {
        float4* hout = (float4*)(g_h + (size_t)n * HH);
#pragma unroll
        for (int jc = 0; jc < 8; jc++) {
            int jc4 = h * 8 + jc;
            float4 hv = s_t1b4[jc4];
#pragma unroll
            for (int i = 0; i < AA; i++) {
                float4 wv = s_t1wT[i * 16 + jc4];
                hv.x += tv[i] * wv.x; hv.y += tv[i] * wv.y;
                hv.z += tv[i] * wv.z; hv.w += tv[i] * wv.w;
            }
            hv.x = fmaxf(hv.x, 0.f); hv.y = fmaxf(hv.y, 0.f);
            hv.z = fmaxf(hv.z, 0.f); hv.w = fmaxf(hv.w, 0.f);
            hout[jc4] = hv;
        }
    }
}

// ---------------- K3: edge kernel — thread-per-edge softmax, f32x2 store -----
__global__ void __launch_bounds__(256)
k_edge(const void* __restrict__ ei, long long E,
       const float* __restrict__ anchor, float* __restrict__ outE) {
    __shared__ unsigned long long s_bp[5][256];   // packed (b,b), column-major
    int tid  = threadIdx.x;
    int lane = tid & 31;
    int warp = tid >> 5;
    int is64 = g_is64;

    // anchor columns 4*lane..4*lane+3 as packed f32x2 pairs, register-resident
    unsigned long long alo[AA], ahi[AA];
#pragma unroll
    for (int k = 0; k < AA; k++) {
        float4 a = __ldg(((const float4*)anchor) + k * 32 + lane);
        alo[k] = packf2(a.x, a.y);
        ahi[k] = packf2(a.z, a.w);
    }

    long long e = (long long)blockIdx.x * 256 + tid;
    if (e < E) {
        int src = ld_edge(ei, e, is64);
        int dst = ld_edge(ei, E + e, is64);
        float4 s4 = __ldg((const float4*)(g_xs8 + (size_t)src * 8));
        float  s5 = __ldg(g_xs8 + (size_t)src * 8 + 4);
        float4 d4 = __ldg((const float4*)(g_xd8 + (size_t)dst * 8));
        float  d5 = __ldg(g_xd8 + (size_t)dst * 8 + 4);
        float l[5];
        l[0] = s4.x + d4.x; l[1] = s4.y + d4.y; l[2] = s4.z + d4.z;
        l[3] = s4.w + d4.w; l[4] = s5 + d5;
#pragma unroll
        for (int k = 0; k < 5; k++) l[k] = fmaxf(l[k], 0.01f * l[k]); // leaky
        float m = l[0];
#pragma unroll
        for (int k = 1; k < 5; k++) m = fmaxf(m, l[k]);
        float ev[5], sum = 0.f;
#pragma unroll
        for (int k = 0; k < 5; k++) { ev[k] = __expf(l[k] - m); sum += ev[k]; }
        float inv = __fdividef(1.0f, sum);
        float b[5];
#pragma unroll
        for (int k = 0; k < 5; k++) b[k] = ev[k] * inv;
        // scatter first 4 components; 5th derived in k_final from degree
        atomicAdd(&g_B4[(size_t)src * 4 + 0], b[0]);
        atomicAdd(&g_B4[(size_t)src * 4 + 1], b[1]);
        atomicAdd(&g_B4[(size_t)src * 4 + 2], b[2]);
        atomicAdd(&g_B4[(size_t)src * 4 + 3], b[3]);
#pragma unroll
        for (int k = 0; k < 5; k++) s_bp[k][tid] = pack2(b[k]);  // conflict-free
    }
    __syncwarp();

    long long base = (long long)blockIdx.x * 256 + warp * 32;
    float4* o4 = (float4*)outE;
#pragma unroll 4
    for (int j = 0; j < 32; j++) {
        long long eid = base + j;
        if (eid >= E) break;
        int sb = warp * 32 + j;                        // uniform -> broadcast
        unsigned long long p0 = s_bp[0][sb], p1 = s_bp[1][sb],
                           p2 = s_bp[2][sb], p3 = s_bp[3][sb], p4 = s_bp[4][sb];
        unsigned long long lo = mul2(p0, alo[0]);
        lo = fma2(p1, alo[1], lo); lo = fma2(p2, alo[2], lo);
        lo = fma2(p3, alo[3], lo); lo = fma2(p4, alo[4], lo);
        unsigned long long hi = mul2(p0, ahi[0]);
        hi = fma2(p1, ahi[1], hi); hi = fma2(p2, ahi[2], hi);
        hi = fma2(p3, ahi[3], hi); hi = fma2(p4, ahi[4], hi);
        float4 o;
        unpack2(lo, o.x, o.y);
        unpack2(hi, o.z, o.w);
        __stcs(o4 + (size_t)eid * 32 + lane, o);  // streaming store
    }
}

// ---------------- K4: final per-node (thread owns one output column) ---------
__global__ void __launch_bounds__(256, 2)
k_final(const float* __restrict__ x,
        const float* __restrict__ node_anchor, const float* __restrict__ anchor,
        const float* __restrict__ t2w, const float* __restrict__ t2b,
        float* __restrict__ outF, int N) {
    int lane = threadIdx.x & 31;
    int gw = (int)((blockIdx.x * blockDim.x + threadIdx.x) >> 5);
    int stream = gw >> 2;
    int cg = gw & 3;
    int nStreams = (int)((gridDim.x * blockDim.x) >> 7);
    int col = cg * 32 + lane;

    float wreg[HH];
#pragma unroll
    for (int j4 = 0; j4 < 16; j4++) {
        float4 wv = ((const float4*)t2w)[(size_t)col * 16 + j4];
        wreg[4*j4+0] = wv.x; wreg[4*j4+1] = wv.y;
        wreg[4*j4+2] = wv.z; wreg[4*j4+3] = wv.w;
    }
    float areg[AA], nareg[AA];
#pragma unroll
    for (int k = 0; k < AA; k++) {
        areg[k]  = __ldg(&anchor[k * DD + col]);
        nareg[k] = __ldg(&node_anchor[k * DD + col]);
    }
    float bias = __ldg(&t2b[col]);

    for (int n = stream; n < N; n += nStreams) {
        float acc = bias;
        const float4* h4 = (const float4*)(g_h + (size_t)n * HH);
#pragma unroll
        for (int j4 = 0; j4 < 16; j4++) {
            float4 hv = h4[j4];      // uniform address -> broadcast
            acc += hv.x * wreg[4*j4+0] + hv.y * wreg[4*j4+1]
                 + hv.z * wreg[4*j4+2] + hv.w * wreg[4*j4+3];
        }
        float4 B   = *(const float4*)(g_B4 + (size_t)n * 4);
        float deg  = (float)g_deg[n];
        float B4v  = deg - B.x - B.y - B.z - B.w;
        float agg  = B.x*areg[0] + B.y*areg[1] + B.z*areg[2] + B.w*areg[3]
                   + B4v*areg[4];
        float4 aw4 = *(const float4*)(g_aw8 + (size_t)n * 8);
        float aw5  = g_aw8[(size_t)n * 8 + 4];
        float np   = aw4.x*nareg[0] + aw4.y*nareg[1] + aw4.z*nareg[2]
                   + aw4.w*nareg[3] + aw5*nareg[4];
        float xv = x[(size_t)n * DD + col];
        outF[(size_t)n * DD + col] = xv + np + acc * agg;
    }
}

// ---------------- launch ------------------------------------------------------
extern "C" void kernel_launch(void* const* d_in, const int* in_sizes, int n_in,
                              void* d_out, int out_size) {
    const float* x           = (const float*)d_in[0];
    const void*  ei          = d_in[1];
    const float* anchor      = (const float*)d_in[3];
    const float* w_w         = (const float*)d_in[4];
    const float* w_b         = (const float*)d_in[5];
    const float* node_anchor = (const float*)d_in[6];
    const float* attn_w      = (const float*)d_in[7];
    const float* attn_b      = (const float*)d_in[8];
    const float* t1w         = (const float*)d_in[9];
    const float* t1b         = (const float*)d_in[10];
    const float* t2w         = (const float*)d_in[11];
    const float* t2b         = (const float*)d_in[12];

    int       N  = in_sizes[0] / DD;
    long long E  = (long long)in_sizes[1] / 2;
    float     Ef = (float)E;

    float* outF = (float*)d_out;                  // final_x [N, D]
    float* outE = outF + (size_t)N * DD;          // edge_prompt [E, D]

    k_init  <<<(N * 4 + 255) / 256, 256>>>((const int*)ei,
                                           (long long)in_sizes[1], N);
    k_degree<<<(unsigned)((E + 255) / 256), 256>>>(ei, E);
    k_nodeA <<<(N + BN - 1) / BN, NT>>>(x, attn_w, attn_b, w_w, w_b,
                                        t1w, t1b, N, Ef);
    k_edge  <<<(unsigned)((E + 255) / 256), 256>>>(ei, E, anchor, outE);
    k_final <<<592, 256>>>(x, node_anchor, anchor, t2w, t2b, outF, N);
}

// round 9
// speedup vs baseline: 1.4057x; 1.1194x over previous
#include <cuda_runtime.h>
#include <cstdint>
#include <cstddef>

// Problem constants (reference: N=50000, D=128, E=800000, A=5)
#define NMAX 50000
#define DD 128
#define AA 5
#define HH 64
#define BN 128   // nodes per block in k_nodeA
#define NT 256   // threads per block in k_nodeA (2 threads per node)

// ---------------- scratch (static device globals) ----------------------------
__device__ __align__(16) float g_B4 [NMAX*4];  // edge softmax sums (4 comps)
__device__ __align__(16) float g_xs8[NMAX*8];  // x @ w[:, :128]^T + bias (pad)
__device__ __align__(16) float g_xd8[NMAX*8];  // x @ w[:, 128:]^T (pad)
__device__ __align__(16) float g_aw8[NMAX*8];  // attention softmax (pad)
__device__ __align__(16) float g_h  [NMAX*HH]; // relu(topo @ t1_w^T + t1_b)
__device__ int   g_deg[NMAX];
__device__ int   g_degmax;
__device__ int   g_is64;

// ---------------- f32x2 packed math helpers ----------------------------------
__device__ __forceinline__ unsigned long long pack2(float v) {
    unsigned long long r;
    asm("mov.b64 %0, {%1, %1};" : "=l"(r) : "f"(v));
    return r;
}
__device__ __forceinline__ unsigned long long packf2(float x, float y) {
    unsigned long long r;
    asm("mov.b64 %0, {%1, %2};" : "=l"(r) : "f"(x), "f"(y));
    return r;
}
__device__ __forceinline__ unsigned long long mul2(unsigned long long a,
                                                   unsigned long long b) {
    unsigned long long d;
    asm("mul.rn.f32x2 %0, %1, %2;" : "=l"(d) : "l"(a), "l"(b));
    return d;
}
__device__ __forceinline__ unsigned long long fma2(unsigned long long a,
                                                   unsigned long long b,
                                                   unsigned long long c) {
    unsigned long long d;
    asm("fma.rn.f32x2 %0, %1, %2, %3;" : "=l"(d) : "l"(a), "l"(b), "l"(c));
    return d;
}
__device__ __forceinline__ void unpack2(unsigned long long v, float& x, float& y) {
    asm("mov.b64 {%0, %1}, %2;" : "=f"(x), "=f"(y) : "l"(v));
}
// vectorized float4 reduction (PTX ISA 8.1+, sm_90+)
__device__ __forceinline__ void red_add_v4(float* p, float b0, float b1,
                                           float b2, float b3) {
    asm volatile(
        "{\n\t.reg .u64 pg;\n\t"
        "cvta.to.global.u64 pg, %0;\n\t"
        "red.global.add.v4.f32 [pg], {%1, %2, %3, %4};\n\t}"
        :: "l"(p), "f"(b0), "f"(b1), "f"(b2), "f"(b3) : "memory");
}

// ---------------- Threefry-2x32 (JAX partitionable semantics) ----------------
__host__ __device__ constexpr unsigned rotl32(unsigned v, int s) {
    return (v << s) | (v >> (32 - s));
}
struct TFout { unsigned a, b; };
__host__ __device__ constexpr TFout tf2x32(unsigned k0, unsigned k1,
                                           unsigned x0, unsigned x1) {
    unsigned ks[3] = {k0, k1, k0 ^ k1 ^ 0x1BD11BDAu};
    const int R0[4] = {13, 15, 26, 6};
    const int R1[4] = {17, 29, 16, 24};
    x0 += ks[0]; x1 += ks[1];
    for (int i = 0; i < 5; i++) {
        for (int j = 0; j < 4; j++) {
            int r = (i % 2 == 0) ? R0[j] : R1[j];
            x0 += x1; x1 = rotl32(x1, r); x1 ^= x0;
        }
        x0 += ks[(i + 1) % 3];
        x1 += ks[(i + 2) % 3] + (unsigned)(i + 1);
    }
    return {x0, x1};
}
// split(key(42)) foldlike: key_i = threefry(key, hi=0, lo=i), both words
constexpr TFout KEY1 = tf2x32(0u, 42u, 0u, 0u);
constexpr TFout KEY2 = tf2x32(0u, 42u, 0u, 1u);

__device__ __forceinline__ float jax_uniform01(unsigned key0, unsigned key1,
                                               unsigned n) {
    TFout r = tf2x32(key0, key1, 0u, n);
    unsigned bits = r.a ^ r.b;
    return __uint_as_float(0x3F800000u | (bits >> 9)) - 1.0f;
}

// ---------------- edge index loader (int32/int64 runtime-detected) ----------
__device__ __forceinline__ int ld_edge(const void* ei, long long pos, int is64) {
    return is64 ? (int)__ldg(((const long long*)ei) + pos)
                : __ldg(((const int*)ei) + pos);
}

// ---------------- K0: zero scratch + detect index dtype ---------------------
__global__ void k_init(const int* ei32, long long n_elems, int N) {
    long long i = (long long)blockIdx.x * blockDim.x + threadIdx.x;
    if (i < (long long)N * 4) g_B4[i] = 0.0f;
    if (i < N)                g_deg[i] = 0;
    if (i == 0) {
        g_degmax = 0;
        long long cnt = n_elems / 2; if (cnt > 64) cnt = 64;
        int orv = 0;
        for (long long t = 0; t < cnt; t++) orv |= ei32[2 * t + 1];
        g_is64 = (orv == 0) ? 1 : 0;
    }
}

// ---------------- K1: degree histogram over src + fused max ------------------
__global__ void __launch_bounds__(256)
k_degree(const void* __restrict__ ei, long long E) {
    int tid = threadIdx.x;
    long long e = (long long)blockIdx.x * 256 + tid;
    int cand = 0;
    if (e < E) {
        int s = ld_edge(ei, e, g_is64);
        cand = atomicAdd(&g_deg[s], 1) + 1;
    }
#pragma unroll
    for (int o = 16; o; o >>= 1)
        cand = max(cand, __shfl_xor_sync(0xffffffffu, cand, o));
    __shared__ int sm[8];
    if ((tid & 31) == 0) sm[tid >> 5] = cand;
    __syncthreads();
    if (tid < 8) {
        int t = sm[tid];
#pragma unroll
        for (int o = 4; o; o >>= 1) t = max(t, __shfl_xor_sync(0xffu, t, o));
        if (tid == 0) atomicMax(&g_degmax, t);
    }
}

// ---------------- K2: per-node precompute (2 threads per node) ----------------
__global__ void __launch_bounds__(NT)
k_nodeA(const float* __restrict__ x,
        const float* __restrict__ attn_w, const float* __restrict__ attn_b,
        const float* __restrict__ w_w,  const float* __restrict__ w_b,
        const float* __restrict__ t1w,  const float* __restrict__ t1b,
        int N, float Ef) {
    __shared__ float  s_x[BN * 33];      // 16.9 KB, conflict-free layout
    __shared__ float4 s_attn[AA * 32];   // [5][128]
    __shared__ float4 s_w[AA * 64];      // [5][256]
    __shared__ float4 s_t1wT[AA * 16];   // transposed [5][64]
    __shared__ float4 s_t1b4[16];
    __shared__ float  s_ab[AA], s_wb[AA];
    int tid = threadIdx.x;
    for (int i = tid; i < AA * 32; i += NT) s_attn[i] = ((const float4*)attn_w)[i];
    for (int i = tid; i < AA * 64; i += NT) s_w[i]    = ((const float4*)w_w)[i];
    for (int idx = tid; idx < AA * HH; idx += NT) {
        int i = idx / HH, j = idx % HH;                // t1w is [64][5]
        ((float*)s_t1wT)[i * HH + j] = t1w[j * AA + i];
    }
    for (int i = tid; i < 16; i += NT) s_t1b4[i] = ((const float4*)t1b)[i];
    if (tid < AA) { s_ab[tid] = attn_b[tid]; s_wb[tid] = w_b[tid]; }
    __syncthreads();

    int nbase = blockIdx.x * BN;
    int r = tid >> 1, h = tid & 1;
    int n = nbase + r;

    float pa[AA], ps[AA], pd[AA];
#pragma unroll
    for (int k = 0; k < AA; k++) { pa[k] = 0.f; ps[k] = 0.f; pd[k] = 0.f; }

    const float4* xg = (const float4*)x;
#pragma unroll
    for (int ch = 0; ch < 4; ch++) {
        if (ch) __syncthreads();
#pragma unroll
        for (int it = 0; it < 4; it++) {
            int idx = it * NT + tid;
            int rr = idx >> 3, c = idx & 7;
            int gn = nbase + rr;
            float4 v = make_float4(0.f, 0.f, 0.f, 0.f);
            if (gn < N) v = __ldg(xg + (size_t)gn * 32 + ch * 8 + c);
            float* p = s_x + rr * 33 + c * 4;
            p[0] = v.x; p[1] = v.y; p[2] = v.z; p[3] = v.w;
        }
        __syncthreads();
        const float* xr = s_x + r * 33 + h * 16;
#pragma unroll
        for (int j = 0; j < 4; j++) {
            float x0 = xr[j*4+0], x1 = xr[j*4+1];
            float x2 = xr[j*4+2], x3 = xr[j*4+3];
            int c = ch * 8 + h * 4 + j;   // halves 16 banks apart: dual-bcast
#pragma unroll
            for (int k = 0; k < AA; k++) {
                float4 av = s_attn[k * 32 + c];
                pa[k] += x0*av.x + x1*av.y + x2*av.z + x3*av.w;
                float4 sv = s_w[k * 64 + c];
                ps[k] += x0*sv.x + x1*sv.y + x2*sv.z + x3*sv.w;
                float4 dv = s_w[k * 64 + 32 + c];
                pd[k] += x0*dv.x + x1*dv.y + x2*dv.z + x3*dv.w;
            }
        }
    }
#pragma unroll
    for (int k = 0; k < AA; k++) {
        pa[k] += __shfl_xor_sync(0xffffffffu, pa[k], 1);
        ps[k] += __shfl_xor_sync(0xffffffffu, ps[k], 1);
        pd[k] += __shfl_xor_sync(0xffffffffu, pd[k], 1);
    }
#pragma unroll
    for (int k = 0; k < AA; k++) { pa[k] += s_ab[k]; ps[k] += s_wb[k]; }

    float m = pa[0];
#pragma unroll
    for (int k = 1; k < AA; k++) m = fmaxf(m, pa[k]);
    float ev[AA], sum = 0.f;
#pragma unroll
    for (int k = 0; k < AA; k++) { ev[k] = __expf(pa[k] - m); sum += ev[k]; }
    float inv = __fdividef(1.0f, sum);

    bool ok = (n < N);
    if (ok && h == 0) {
        *(float4*)(g_aw8 + (size_t)n * 8) =
            make_float4(ev[0]*inv, ev[1]*inv, ev[2]*inv, ev[3]*inv);
        g_aw8[(size_t)n * 8 + 4] = ev[4] * inv;
        *(float4*)(g_xs8 + (size_t)n * 8) = make_float4(ps[0], ps[1], ps[2], ps[3]);
        g_xs8[(size_t)n * 8 + 4] = ps[4];
    }
    if (ok && h == 1) {
        *(float4*)(g_xd8 + (size_t)n * 8) = make_float4(pd[0], pd[1], pd[2], pd[3]);
        g_xd8[(size_t)n * 8 + 4] = pd[4];
    }

    // topology features + hidden layer
    int nc = (n < N) ? n : (N - 1);
    float deg   = (float)__ldg(&g_deg[nc]);
    float dmaxf = (float)g_degmax;
    float meanf = Ef / (float)N;
    unsigned kk0 = h ? KEY2.a : KEY1.a;
    unsigned kk1 = h ? KEY2.b : KEY1.b;
    float u_own   = jax_uniform01(kk0, kk1, (unsigned)n);
    float u_other = __shfl_xor_sync(0xffffffffu, u_own, 1);
    float u1 = h ? u_other : u_own;   // KEY1 stream
    float u2 = h ? u_own   : u_other; // KEY2 stream

    float tv[5];
    tv[0] = deg / (dmaxf + 1e-6f);
    tv[1] = u1 * 0.5f + 0.25f;
    tv[2] = deg / (Ef + 1e-6f);
    tv[3] = 1.0f / (1.0f + __expf(-(deg - meanf)));
    tv[4] = u2;

    if (ok) {
        float4* hout = (float4*)(g_h + (size_t)n * HH);
#pragma unroll
        for (int jc = 0; jc < 8; jc++) {
            int jc4 = h * 8 + jc;
            float4 hv = s_t1b4[jc4];
#pragma unroll
            for (int i = 0; i < AA; i++) {
                float4 wv = s_t1wT[i * 16 + jc4];
                hv.x += tv[i] * wv.x; hv.y += tv[i] * wv.y;
                hv.z += tv[i] * wv.z; hv.w += tv[i] * wv.w;
            }
            hv.x = fmaxf(hv.x, 0.f); hv.y = fmaxf(hv.y, 0.f);
            hv.z = fmaxf(hv.z, 0.f); hv.w = fmaxf(hv.w, 0.f);
            hout[jc4] = hv;
        }
    }
}

// ---------------- K3: edge kernel — thread-per-edge softmax, f32x2 store -----
__global__ void __launch_bounds__(256)
k_edge(const void* __restrict__ ei, long long E,
       const float* __restrict__ anchor, float* __restrict__ outE) {
    __shared__ unsigned long long s_bp[5][256];   // packed (b,b), column-major
    int tid  = threadIdx.x;
    int lane = tid & 31;
    int warp = tid >> 5;
    int is64 = g_is64;

    unsigned long long alo[AA], ahi[AA];
#pragma unroll
    for (int k = 0; k < AA; k++) {
        float4 a = __ldg(((const float4*)anchor) + k * 32 + lane);
        alo[k] = packf2(a.x, a.y);
        ahi[k] = packf2(a.z, a.w);
    }

    long long e = (long long)blockIdx.x * 256 + tid;
    if (e < E) {
        int src = ld_edge(ei, e, is64);
        int dst = ld_edge(ei, E + e, is64);
        float4 s4 = __ldg((const float4*)(g_xs8 + (size_t)src * 8));
        float  s5 = __ldg(g_xs8 + (size_t)src * 8 + 4);
        float4 d4 = __ldg((const float4*)(g_xd8 + (size_t)dst * 8));
        float  d5 = __ldg(g_xd8 + (size_t)dst * 8 + 4);
        float l[5];
        l[0] = s4.x + d4.x; l[1] = s4.y + d4.y; l[2] = s4.z + d4.z;
        l[3] = s4.w + d4.w; l[4] = s5 + d5;
#pragma unroll
        for (int k = 0; k < 5; k++) l[k] = fmaxf(l[k], 0.01f * l[k]); // leaky
        float m = l[0];
#pragma unroll
        for (int k = 1; k < 5; k++) m = fmaxf(m, l[k]);
        float ev[5], sum = 0.f;
#pragma unroll
        for (int k = 0; k < 5; k++) { ev[k] = __expf(l[k] - m); sum += ev[k]; }
        float inv = __fdividef(1.0f, sum);
        float b[5];
#pragma unroll
        for (int k = 0; k < 5; k++) b[k] = ev[k] * inv;
        // one vectorized reduction for 4 comps; 5th derived in k_final
        red_add_v4(g_B4 + (size_t)src * 4, b[0], b[1], b[2], b[3]);
#pragma unroll
        for (int k = 0; k < 5; k++) s_bp[k][tid] = pack2(b[k]);  // conflict-free
    }
    __syncwarp();

    long long base = (long long)blockIdx.x * 256 + warp * 32;
    float4* o4 = (float4*)outE;
#pragma unroll 4
    for (int j = 0; j < 32; j++) {
        long long eid = base + j;
        if (eid >= E) break;
        int sb = warp * 32 + j;                        // uniform -> broadcast
        unsigned long long p0 = s_bp[0][sb], p1 = s_bp[1][sb],
                           p2 = s_bp[2][sb], p3 = s_bp[3][sb], p4 = s_bp[4][sb];
        unsigned long long lo = mul2(p0, alo[0]);
        lo = fma2(p1, alo[1], lo); lo = fma2(p2, alo[2], lo);
        lo = fma2(p3, alo[3], lo); lo = fma2(p4, alo[4], lo);
        unsigned long long hi = mul2(p0, ahi[0]);
        hi = fma2(p1, ahi[1], hi); hi = fma2(p2, ahi[2], hi);
        hi = fma2(p3, ahi[3], hi); hi = fma2(p4, ahi[4], hi);
        float4 o;
        unpack2(lo, o.x, o.y);
        unpack2(hi, o.z, o.w);
        __stcs(o4 + (size_t)eid * 32 + lane, o);  // streaming store
    }
}

// ---------------- K4: final per-node (f32x2 packed GEMM) ----------------------
__global__ void __launch_bounds__(256, 2)
k_final(const float* __restrict__ x,
        const float* __restrict__ node_anchor, const float* __restrict__ anchor,
        const float* __restrict__ t2w, const float* __restrict__ t2b,
        float* __restrict__ outF, int N) {
    int lane = threadIdx.x & 31;
    int gw = (int)((blockIdx.x * blockDim.x + threadIdx.x) >> 5);
    int stream = gw >> 2;
    int cg = gw & 3;
    int nStreams = (int)((gridDim.x * blockDim.x) >> 7);
    int col = cg * 32 + lane;

    // t2_w row for this column, packed as 32 (w[2j], w[2j+1]) f32x2 pairs
    unsigned long long wp[32];
#pragma unroll
    for (int j4 = 0; j4 < 16; j4++) {
        float4 wv = ((const float4*)t2w)[(size_t)col * 16 + j4];
        wp[2*j4+0] = packf2(wv.x, wv.y);
        wp[2*j4+1] = packf2(wv.z, wv.w);
    }
    float areg[AA], nareg[AA];
#pragma unroll
    for (int k = 0; k < AA; k++) {
        areg[k]  = __ldg(&anchor[k * DD + col]);
        nareg[k] = __ldg(&node_anchor[k * DD + col]);
    }
    float bias = __ldg(&t2b[col]);

    for (int n = stream; n < N; n += nStreams) {
        // g_h row: 64 floats = 32 u64 pairs = 16 ulonglong2 vectors.
        // pair index p = 2*jc (hv.x) and 2*jc+1 (hv.y) matches wp[p] exactly.
        const ulonglong2* h2 = (const ulonglong2*)(g_h + (size_t)n * HH);
        unsigned long long acc2 = 0ULL;   // bits of (0.f, 0.f)
#pragma unroll
        for (int jc = 0; jc < 16; jc++) {
            ulonglong2 hv = h2[jc];        // uniform address -> broadcast
            acc2 = fma2(hv.x, wp[2*jc+0], acc2);
            acc2 = fma2(hv.y, wp[2*jc+1], acc2);
        }
        float aclo, achi;
        unpack2(acc2, aclo, achi);
        float acc = bias + aclo + achi;

        float4 B   = *(const float4*)(g_B4 + (size_t)n * 4);
        float deg  = (float)g_deg[n];
        float B4v  = deg - B.x - B.y - B.z - B.w;
        float agg  = B.x*areg[0] + B.y*areg[1] + B.z*areg[2] + B.w*areg[3]
                   + B4v*areg[4];
        float4 aw4 = *(const float4*)(g_aw8 + (size_t)n * 8);
        float aw5  = g_aw8[(size_t)n * 8 + 4];
        float np   = aw4.x*nareg[0] + aw4.y*nareg[1] + aw4.z*nareg[2]
                   + aw4.w*nareg[3] + aw5*nareg[4];
        float xv = x[(size_t)n * DD + col];
        outF[(size_t)n * DD + col] = xv + np + acc * agg;
    }
}

// ---------------- launch ------------------------------------------------------
extern "C" void kernel_launch(void* const* d_in, const int* in_sizes, int n_in,
                              void* d_out, int out_size) {
    const float* x           = (const float*)d_in[0];
    const void*  ei          = d_in[1];
    const float* anchor      = (const float*)d_in[3];
    const float* w_w         = (const float*)d_in[4];
    const float* w_b         = (const float*)d_in[5];
    const float* node_anchor = (const float*)d_in[6];
    const float* attn_w      = (const float*)d_in[7];
    const float* attn_b      = (const float*)d_in[8];
    const float* t1w         = (const float*)d_in[9];
    const float* t1b         = (const float*)d_in[10];
    const float* t2w         = (const float*)d_in[11];
    const float* t2b         = (const float*)d_in[12];

    int       N  = in_sizes[0] / DD;
    long long E  = (long long)in_sizes[1] / 2;
    float     Ef = (float)E;

    float* outF = (float*)d_out;                  // final_x [N, D]
    float* outE = outF + (size_t)N * DD;          // edge_prompt [E, D]

    k_init  <<<(N * 4 + 255) / 256, 256>>>((const int*)ei,
                                           (long long)in_sizes[1], N);
    k_degree<<<(unsigned)((E + 255) / 256), 256>>>(ei, E);
    k_nodeA <<<(N + BN - 1) / BN, NT>>>(x, attn_w, attn_b, w_w, w_b,
                                        t1w, t1b, N, Ef);
    k_edge  <<<(unsigned)((E + 255) / 256), 256>>>(ei, E, anchor, outE);
    k_final <<<592, 256>>>(x, node_anchor, anchor, t2w, t2b, outF, N);
}

// round 10
// speedup vs baseline: 1.4241x; 1.0130x over previous
#include <cuda_runtime.h>
#include <cstdint>
#include <cstddef>

// Problem constants (reference: N=50000, D=128, E=800000, A=5)
#define NMAX 50000
#define DD 128
#define AA 5
#define HH 64
#define BN 64    // nodes per block in k_nodeA
#define NT 128   // threads per block in k_nodeA (2 threads per node)

// ---------------- scratch (static device globals) ----------------------------
__device__ __align__(16) float g_B4 [NMAX*4];  // edge softmax sums (4 comps)
__device__ __align__(16) float g_xs8[NMAX*8];  // x @ w[:, :128]^T + bias (pad)
__device__ __align__(16) float g_xd8[NMAX*8];  // x @ w[:, 128:]^T (pad)
__device__ __align__(16) float g_aw8[NMAX*8];  // attention softmax (pad)
__device__ __align__(16) float g_h  [NMAX*HH]; // relu(topo @ t1_w^T + t1_b)
__device__ int   g_deg[NMAX];
__device__ int   g_degmax;
__device__ int   g_is64;

// ---------------- f32x2 packed math helpers ----------------------------------
__device__ __forceinline__ unsigned long long pack2(float v) {
    unsigned long long r;
    asm("mov.b64 %0, {%1, %1};" : "=l"(r) : "f"(v));
    return r;
}
__device__ __forceinline__ unsigned long long packf2(float x, float y) {
    unsigned long long r;
    asm("mov.b64 %0, {%1, %2};" : "=l"(r) : "f"(x), "f"(y));
    return r;
}
__device__ __forceinline__ unsigned long long mul2(unsigned long long a,
                                                   unsigned long long b) {
    unsigned long long d;
    asm("mul.rn.f32x2 %0, %1, %2;" : "=l"(d) : "l"(a), "l"(b));
    return d;
}
__device__ __forceinline__ unsigned long long fma2(unsigned long long a,
                                                   unsigned long long b,
                                                   unsigned long long c) {
    unsigned long long d;
    asm("fma.rn.f32x2 %0, %1, %2, %3;" : "=l"(d) : "l"(a), "l"(b), "l"(c));
    return d;
}
__device__ __forceinline__ void unpack2(unsigned long long v, float& x, float& y) {
    asm("mov.b64 {%0, %1}, %2;" : "=f"(x), "=f"(y) : "l"(v));
}
// vectorized float4 reduction (PTX ISA 8.1+, sm_90+)
__device__ __forceinline__ void red_add_v4(float* p, float b0, float b1,
                                           float b2, float b3) {
    asm volatile(
        "{\n\t.reg .u64 pg;\n\t"
        "cvta.to.global.u64 pg, %0;\n\t"
        "red.global.add.v4.f32 [pg], {%1, %2, %3, %4};\n\t}"
        :: "l"(p), "f"(b0), "f"(b1), "f"(b2), "f"(b3) : "memory");
}

// ---------------- Threefry-2x32 (JAX partitionable semantics) ----------------
__host__ __device__ constexpr unsigned rotl32(unsigned v, int s) {
    return (v << s) | (v >> (32 - s));
}
struct TFout { unsigned a, b; };
__host__ __device__ constexpr TFout tf2x32(unsigned k0, unsigned k1,
                                           unsigned x0, unsigned x1) {
    unsigned ks[3] = {k0, k1, k0 ^ k1 ^ 0x1BD11BDAu};
    const int R0[4] = {13, 15, 26, 6};
    const int R1[4] = {17, 29, 16, 24};
    x0 += ks[0]; x1 += ks[1];
    for (int i = 0; i < 5; i++) {
        for (int j = 0; j < 4; j++) {
            int r = (i % 2 == 0) ? R0[j] : R1[j];
            x0 += x1; x1 = rotl32(x1, r); x1 ^= x0;
        }
        x0 += ks[(i + 1) % 3];
        x1 += ks[(i + 2) % 3] + (unsigned)(i + 1);
    }
    return {x0, x1};
}
// split(key(42)) foldlike: key_i = threefry(key, hi=0, lo=i), both words
constexpr TFout KEY1 = tf2x32(0u, 42u, 0u, 0u);
constexpr TFout KEY2 = tf2x32(0u, 42u, 0u, 1u);

__device__ __forceinline__ float jax_uniform01(unsigned key0, unsigned key1,
                                               unsigned n) {
    TFout r = tf2x32(key0, key1, 0u, n);
    unsigned bits = r.a ^ r.b;
    return __uint_as_float(0x3F800000u | (bits >> 9)) - 1.0f;
}

// ---------------- edge index loader (int32/int64 runtime-detected) ----------
__device__ __forceinline__ int ld_edge(const void* ei, long long pos, int is64) {
    return is64 ? (int)__ldg(((const long long*)ei) + pos)
                : __ldg(((const int*)ei) + pos);
}

// ---------------- K0: zero scratch + detect index dtype ---------------------
__global__ void k_init(const int* ei32, long long n_elems, int N) {
    long long i = (long long)blockIdx.x * blockDim.x + threadIdx.x;
    if (i < (long long)N * 4) g_B4[i] = 0.0f;
    if (i < N)                g_deg[i] = 0;
    if (i == 0) {
        g_degmax = 0;
        long long cnt = n_elems / 2; if (cnt > 64) cnt = 64;
        int orv = 0;
        for (long long t = 0; t < cnt; t++) orv |= ei32[2 * t + 1];
        g_is64 = (orv == 0) ? 1 : 0;
    }
}

// ---------------- K1: degree histogram over src + fused max ------------------
__global__ void __launch_bounds__(256)
k_degree(const void* __restrict__ ei, long long E) {
    int tid = threadIdx.x;
    long long e = (long long)blockIdx.x * 256 + tid;
    int cand = 0;
    if (e < E) {
        int s = ld_edge(ei, e, g_is64);
        cand = atomicAdd(&g_deg[s], 1) + 1;
    }
#pragma unroll
    for (int o = 16; o; o >>= 1)
        cand = max(cand, __shfl_xor_sync(0xffffffffu, cand, o));
    __shared__ int sm[8];
    if ((tid & 31) == 0) sm[tid >> 5] = cand;
    __syncthreads();
    if (tid < 8) {
        int t = sm[tid];
#pragma unroll
        for (int o = 4; o; o >>= 1) t = max(t, __shfl_xor_sync(0xffu, t, o));
        if (tid == 0) atomicMax(&g_degmax, t);
    }
}

// ---------------- K2: per-node precompute (2 threads per node) ----------------
// BN=64 nodes/block, NT=128 threads: grid 782 blocks for occupancy.
__global__ void __launch_bounds__(NT)
k_nodeA(const float* __restrict__ x,
        const float* __restrict__ attn_w, const float* __restrict__ attn_b,
        const float* __restrict__ w_w,  const float* __restrict__ w_b,
        const float* __restrict__ t1w,  const float* __restrict__ t1b,
        int N, float Ef) {
    __shared__ float  s_x[BN * 33];      // 8.4 KB, conflict-free layout
    __shared__ float4 s_attn[AA * 32];   // [5][128]
    __shared__ float4 s_w[AA * 64];      // [5][256]
    __shared__ float4 s_t1wT[AA * 16];   // transposed [5][64]
    __shared__ float4 s_t1b4[16];
    __shared__ float  s_ab[AA], s_wb[AA];
    int tid = threadIdx.x;
    for (int i = tid; i < AA * 32; i += NT) s_attn[i] = ((const float4*)attn_w)[i];
    for (int i = tid; i < AA * 64; i += NT) s_w[i]    = ((const float4*)w_w)[i];
    for (int idx = tid; idx < AA * HH; idx += NT) {
        int i = idx / HH, j = idx % HH;                // t1w is [64][5]
        ((float*)s_t1wT)[i * HH + j] = t1w[j * AA + i];
    }
    for (int i = tid; i < 16; i += NT) s_t1b4[i] = ((const float4*)t1b)[i];
    if (tid < AA) { s_ab[tid] = attn_b[tid]; s_wb[tid] = w_b[tid]; }
    __syncthreads();

    int nbase = blockIdx.x * BN;
    int r = tid >> 1, h = tid & 1;
    int n = nbase + r;

    float pa[AA], ps[AA], pd[AA];
#pragma unroll
    for (int k = 0; k < AA; k++) { pa[k] = 0.f; ps[k] = 0.f; pd[k] = 0.f; }

    const float4* xg = (const float4*)x;
#pragma unroll
    for (int ch = 0; ch < 4; ch++) {
        if (ch) __syncthreads();
        // stage BN rows x 8 float4 (this chunk), coalesced: 4 f4 per thread
#pragma unroll
        for (int it = 0; it < 4; it++) {
            int idx = it * NT + tid;
            int rr = idx >> 3, c = idx & 7;
            int gn = nbase + rr;
            float4 v = make_float4(0.f, 0.f, 0.f, 0.f);
            if (gn < N) v = __ldg(xg + (size_t)gn * 32 + ch * 8 + c);
            float* p = s_x + rr * 33 + c * 4;
            p[0] = v.x; p[1] = v.y; p[2] = v.z; p[3] = v.w;
        }
        __syncthreads();
        const float* xr = s_x + r * 33 + h * 16;
#pragma unroll
        for (int j = 0; j < 4; j++) {
            float x0 = xr[j*4+0], x1 = xr[j*4+1];
            float x2 = xr[j*4+2], x3 = xr[j*4+3];
            int c = ch * 8 + h * 4 + j;   // halves 16 banks apart: dual-bcast
#pragma unroll
            for (int k = 0; k < AA; k++) {
                float4 av = s_attn[k * 32 + c];
                pa[k] += x0*av.x + x1*av.y + x2*av.z + x3*av.w;
                float4 sv = s_w[k * 64 + c];
                ps[k] += x0*sv.x + x1*sv.y + x2*sv.z + x3*sv.w;
                float4 dv = s_w[k * 64 + 32 + c];
                pd[k] += x0*dv.x + x1*dv.y + x2*dv.z + x3*dv.w;
            }
        }
    }
#pragma unroll
    for (int k = 0; k < AA; k++) {
        pa[k] += __shfl_xor_sync(0xffffffffu, pa[k], 1);
        ps[k] += __shfl_xor_sync(0xffffffffu, ps[k], 1);
        pd[k] += __shfl_xor_sync(0xffffffffu, pd[k], 1);
    }
#pragma unroll
    for (int k = 0; k < AA; k++) { pa[k] += s_ab[k]; ps[k] += s_wb[k]; }

    float m = pa[0];
#pragma unroll
    for (int k = 1; k < AA; k++) m = fmaxf(m, pa[k]);
    float ev[AA], sum = 0.f;
#pragma unroll
    for (int k = 0; k < AA; k++) { ev[k] = __expf(pa[k] - m); sum += ev[k]; }
    float inv = __fdividef(1.0f, sum);

    bool ok = (n < N);
    if (ok && h == 0) {
        *(float4*)(g_aw8 + (size_t)n * 8) =
            make_float4(ev[0]*inv, ev[1]*inv, ev[2]*inv, ev[3]*inv);
        g_aw8[(size_t)n * 8 + 4] = ev[4] * inv;
        *(float4*)(g_xs8 + (size_t)n * 8) = make_float4(ps[0], ps[1], ps[2], ps[3]);
        g_xs8[(size_t)n * 8 + 4] = ps[4];
    }
    if (ok && h == 1) {
        *(float4*)(g_xd8 + (size_t)n * 8) = make_float4(pd[0], pd[1], pd[2], pd[3]);
        g_xd8[(size_t)n * 8 + 4] = pd[4];
    }

    // topology features + hidden layer
    int nc = (n < N) ? n : (N - 1);
    float deg   = (float)__ldg(&g_deg[nc]);
    float dmaxf = (float)g_degmax;
    float meanf = Ef / (float)N;
    unsigned kk0 = h ? KEY2.a : KEY1.a;
    unsigned kk1 = h ? KEY2.b : KEY1.b;
    float u_own   = jax_uniform01(kk0, kk1, (unsigned)n);
    float u_other = __shfl_xor_sync(0xffffffffu, u_own, 1);
    float u1 = h ? u_other : u_own;   // KEY1 stream
    float u2 = h ? u_own   : u_other; // KEY2 stream

    float tv[5];
    tv[0] = deg / (dmaxf + 1e-6f);
    tv[1] = u1 * 0.5f + 0.25f;
    tv[2] = deg / (Ef + 1e-6f);
    tv[3] = 1.0f / (1.0f + __expf(-(deg - meanf)));
    tv[4] = u2;

    if (ok) {
        float4* hout = (float4*)(g_h + (size_t)n * HH);
#pragma unroll
        for (int jc = 0; jc < 8; jc++) {
            int jc4 = h * 8 + jc;
            float4 hv = s_t1b4[jc4];
#pragma unroll
            for (int i = 0; i < AA; i++) {
                float4 wv = s_t1wT[i * 16 + jc4];
                hv.x += tv[i] * wv.x; hv.y += tv[i] * wv.y;
                hv.z += tv[i] * wv.z; hv.w += tv[i] * wv.w;
            }
            hv.x = fmaxf(hv.x, 0.f); hv.y = fmaxf(hv.y, 0.f);
            hv.z = fmaxf(hv.z, 0.f); hv.w = fmaxf(hv.w, 0.f);
            hout[jc4] = hv;
        }
    }
}

// ---------------- K3: edge kernel — thread-per-edge softmax, f32x2 store -----
__global__ void __launch_bounds__(256)
k_edge(const void* __restrict__ ei, long long E,
       const float* __restrict__ anchor, float* __restrict__ outE) {
    __shared__ unsigned long long s_bp[5][256];   // packed (b,b), column-major
    int tid  = threadIdx.x;
    int lane = tid & 31;
    int warp = tid >> 5;
    int is64 = g_is64;

    unsigned long long alo[AA], ahi[AA];
#pragma unroll
    for (int k = 0; k < AA; k++) {
        float4 a = __ldg(((const float4*)anchor) + k * 32 + lane);
        alo[k] = packf2(a.x, a.y);
        ahi[k] = packf2(a.z, a.w);
    }

    long long e = (long long)blockIdx.x * 256 + tid;
    if (e < E) {
        int src = ld_edge(ei, e, is64);
        int dst = ld_edge(ei, E + e, is64);
        float4 s4 = __ldg((const float4*)(g_xs8 + (size_t)src * 8));
        float  s5 = __ldg(g_xs8 + (size_t)src * 8 + 4);
        float4 d4 = __ldg((const float4*)(g_xd8 + (size_t)dst * 8));
        float  d5 = __ldg(g_xd8 + (size_t)dst * 8 + 4);
        float l[5];
        l[0] = s4.x + d4.x; l[1] = s4.y + d4.y; l[2] = s4.z + d4.z;
        l[3] = s4.w + d4.w; l[4] = s5 + d5;
#pragma unroll
        for (int k = 0; k < 5; k++) l[k] = fmaxf(l[k], 0.01f * l[k]); // leaky
        float m = l[0];
#pragma unroll
        for (int k = 1; k < 5; k++) m = fmaxf(m, l[k]);
        float ev[5], sum = 0.f;
#pragma unroll
        for (int k = 0; k < 5; k++) { ev[k] = __expf(l[k] - m); sum += ev[k]; }
        float inv = __fdividef(1.0f, sum);
        float b[5];
#pragma unroll
        for (int k = 0; k < 5; k++) b[k] = ev[k] * inv;
        // one vectorized reduction for 4 comps; 5th derived in k_final
        red_add_v4(g_B4 + (size_t)src * 4, b[0], b[1], b[2], b[3]);
#pragma unroll
        for (int k = 0; k < 5; k++) s_bp[k][tid] = pack2(b[k]);  // conflict-free
    }
    __syncwarp();

    long long base = (long long)blockIdx.x * 256 + warp * 32;
    float4* o4 = (float4*)outE;
    int nfull = (base + 32 <= E) ? 32 : (int)(E > base ? E - base : 0);
    if (nfull == 32) {
        // fast path: no per-iteration bound check (E % 256 == 0 typical)
#pragma unroll 4
        for (int j = 0; j < 32; j++) {
            int sb = warp * 32 + j;                    // uniform -> broadcast
            unsigned long long p0 = s_bp[0][sb], p1 = s_bp[1][sb],
                               p2 = s_bp[2][sb], p3 = s_bp[3][sb],
                               p4 = s_bp[4][sb];
            unsigned long long lo = mul2(p0, alo[0]);
            lo = fma2(p1, alo[1], lo); lo = fma2(p2, alo[2], lo);
            lo = fma2(p3, alo[3], lo); lo = fma2(p4, alo[4], lo);
            unsigned long long hi = mul2(p0, ahi[0]);
            hi = fma2(p1, ahi[1], hi); hi = fma2(p2, ahi[2], hi);
            hi = fma2(p3, ahi[3], hi); hi = fma2(p4, ahi[4], hi);
            float4 o;
            unpack2(lo, o.x, o.y);
            unpack2(hi, o.z, o.w);
            __stcs(o4 + (size_t)(base + j) * 32 + lane, o);
        }
    } else {
        for (int j = 0; j < nfull; j++) {
            int sb = warp * 32 + j;
            unsigned long long p0 = s_bp[0][sb], p1 = s_bp[1][sb],
                               p2 = s_bp[2][sb], p3 = s_bp[3][sb],
                               p4 = s_bp[4][sb];
            unsigned long long lo = mul2(p0, alo[0]);
            lo = fma2(p1, alo[1], lo); lo = fma2(p2, alo[2], lo);
            lo = fma2(p3, alo[3], lo); lo = fma2(p4, alo[4], lo);
            unsigned long long hi = mul2(p0, ahi[0]);
            hi = fma2(p1, ahi[1], hi); hi = fma2(p2, ahi[2], hi);
            hi = fma2(p3, ahi[3], hi); hi = fma2(p4, ahi[4], hi);
            float4 o;
            unpack2(lo, o.x, o.y);
            unpack2(hi, o.z, o.w);
            __stcs(o4 + (size_t)(base + j) * 32 + lane, o);
        }
    }
}

// ---------------- K4: final per-node (f32x2 packed GEMM) ----------------------
__global__ void __launch_bounds__(256, 2)
k_final(const float* __restrict__ x,
        const float* __restrict__ node_anchor, const float* __restrict__ anchor,
        const float* __restrict__ t2w, const float* __restrict__ t2b,
        float* __restrict__ outF, int N) {
    int lane = threadIdx.x & 31;
    int gw = (int)((blockIdx.x * blockDim.x + threadIdx.x) >> 5);
    int stream = gw >> 2;
    int cg = gw & 3;
    int nStreams = (int)((gridDim.x * blockDim.x) >> 7);
    int col = cg * 32 + lane;

    // t2_w row for this column, packed as 32 (w[2j], w[2j+1]) f32x2 pairs
    unsigned long long wp[32];
#pragma unroll
    for (int j4 = 0; j4 < 16; j4++) {
        float4 wv = ((const float4*)t2w)[(size_t)col * 16 + j4];
        wp[2*j4+0] = packf2(wv.x, wv.y);
        wp[2*j4+1] = packf2(wv.z, wv.w);
    }
    float areg[AA], nareg[AA];
#pragma unroll
    for (int k = 0; k < AA; k++) {
        areg[k]  = __ldg(&anchor[k * DD + col]);
        nareg[k] = __ldg(&node_anchor[k * DD + col]);
    }
    float bias = __ldg(&t2b[col]);

    for (int n = stream; n < N; n += nStreams) {
        // g_h row: 64 floats = 32 u64 pairs = 16 ulonglong2 vectors.
        const ulonglong2* h2 = (const ulonglong2*)(g_h + (size_t)n * HH);
        unsigned long long acc2 = 0ULL;   // bits of (0.f, 0.f)
#pragma unroll
        for (int jc = 0; jc < 16; jc++) {
            ulonglong2 hv = h2[jc];        // uniform address -> broadcast
            acc2 = fma2(hv.x, wp[2*jc+0], acc2);
            acc2 = fma2(hv.y, wp[2*jc+1], acc2);
        }
        float aclo, achi;
        unpack2(acc2, aclo, achi);
        float acc = bias + aclo + achi;

        float4 B   = *(const float4*)(g_B4 + (size_t)n * 4);
        float deg  = (float)g_deg[n];
        float B4v  = deg - B.x - B.y - B.z - B.w;
        float agg  = B.x*areg[0] + B.y*areg[1] + B.z*areg[2] + B.w*areg[3]
                   + B4v*areg[4];
        float4 aw4 = *(const float4*)(g_aw8 + (size_t)n * 8);
        float aw5  = g_aw8[(size_t)n * 8 + 4];
        float np   = aw4.x*nareg[0] + aw4.y*nareg[1] + aw4.z*nareg[2]
                   + aw4.w*nareg[3] + aw5*nareg[4];
        float xv = x[(size_t)n * DD + col];
        outF[(size_t)n * DD + col] = xv + np + acc * agg;
    }
}

// ---------------- launch ------------------------------------------------------
extern "C" void kernel_launch(void* const* d_in, const int* in_sizes, int n_in,
                              void* d_out, int out_size) {
    const float* x           = (const float*)d_in[0];
    const void*  ei          = d_in[1];
    const float* anchor      = (const float*)d_in[3];
    const float* w_w         = (const float*)d_in[4];
    const float* w_b         = (const float*)d_in[5];
    const float* node_anchor = (const float*)d_in[6];
    const float* attn_w      = (const float*)d_in[7];
    const float* attn_b      = (const float*)d_in[8];
    const float* t1w         = (const float*)d_in[9];
    const float* t1b         = (const float*)d_in[10];
    const float* t2w         = (const float*)d_in[11];
    const float* t2b         = (const float*)d_in[12];

    int       N  = in_sizes[0] / DD;
    long long E  = (long long)in_sizes[1] / 2;
    float     Ef = (float)E;

    float* outF = (float*)d_out;                  // final_x [N, D]
    float* outE = outF + (size_t)N * DD;          // edge_prompt [E, D]

    k_init  <<<(N * 4 + 255) / 256, 256>>>((const int*)ei,
                                           (long long)in_sizes[1], N);
    k_degree<<<(unsigned)((E + 255) / 256), 256>>>(ei, E);
    k_nodeA <<<(N + BN - 1) / BN, NT>>>(x, attn_w, attn_b, w_w, w_b,
                                        t1w, t1b, N, Ef);
    k_edge  <<<(unsigned)((E + 255) / 256), 256>>>(ei, E, anchor, outE);
    k_final <<<592, 256>>>(x, node_anchor, anchor, t2w, t2b, outF, N);
}